// round 10
// baseline (speedup 1.0000x reference)
#include <cuda_runtime.h>
#include <math.h>
#include <cstdint>

#define NN 256
#define DD 64
#define BB 2048
#define RANK_K 52428          // int(0.8 * 256 * 256)
#define NCHUNK 32             // node chunks; 8 nodes per chunk
#define FB 16                 // kfinal rows per block

// ---------------- scratch (device globals; no allocation allowed) ------------
__device__ float g_thr;
__device__ float g_adj[NN * NN];
__device__ float g_eff[NN * DD * DD];                  // 4 MB
__device__ float g_parts[(size_t)NCHUNK * BB * DD];    // 16.8 MB
__device__ unsigned g_hist16[65536];

// ---------------- smem map for mma kernel (dynamic) --------------------------
#define SM_XHI  0                        // 128x64 bf16, SW128-swizzled rows of 128B
#define SM_XLO  16384
#define SM_WHI  32768                    // 64x64 bf16 [k][n] row-major swizzled
#define SM_WLO  40960
#define SM_BIAS 49152                    // 128 floats: bias1[64], bias2[64]
#define SM_TOT  49664

// ---------------- helpers -----------------------------------------------------
__device__ __forceinline__ uint32_t smem_u32(const void* p) {
    uint32_t a;
    asm("{ .reg .u64 t; cvta.to.shared.u64 t, %1; cvt.u32.u64 %0, t; }" : "=r"(a) : "l"(p));
    return a;
}
__device__ __forceinline__ uint32_t sw128(uint32_t o) { return o ^ ((o >> 3) & 0x70u); }

__device__ __forceinline__ void ldm_x4(uint32_t r[4], uint32_t addr) {
    asm volatile("ldmatrix.sync.aligned.m8n8.x4.shared.b16 {%0,%1,%2,%3}, [%4];"
                 : "=r"(r[0]), "=r"(r[1]), "=r"(r[2]), "=r"(r[3]) : "r"(addr));
}
__device__ __forceinline__ void ldm_x4_t(uint32_t r[4], uint32_t addr) {
    asm volatile("ldmatrix.sync.aligned.m8n8.x4.trans.shared.b16 {%0,%1,%2,%3}, [%4];"
                 : "=r"(r[0]), "=r"(r[1]), "=r"(r[2]), "=r"(r[3]) : "r"(addr));
}
__device__ __forceinline__ void mma16816(float c[4], const uint32_t a[4], const uint32_t b[2]) {
    asm volatile(
        "mma.sync.aligned.m16n8k16.row.col.f32.bf16.bf16.f32 "
        "{%0,%1,%2,%3}, {%4,%5,%6,%7}, {%8,%9}, {%0,%1,%2,%3};"
        : "+f"(c[0]), "+f"(c[1]), "+f"(c[2]), "+f"(c[3])
        : "r"(a[0]), "r"(a[1]), "r"(a[2]), "r"(a[3]), "r"(b[0]), "r"(b[1]));
}
// pack (x0,x1) -> bf16 hi pair + bf16 lo-residual pair (memory order: x0 low half)
__device__ __forceinline__ void split2(float x0, float x1, uint32_t& hi, uint32_t& lo) {
    uint32_t h;
    asm("cvt.rn.bf16x2.f32 %0, %1, %2;" : "=r"(h) : "f"(x1), "f"(x0));
    float h0 = __uint_as_float(h << 16);
    float h1 = __uint_as_float(h & 0xffff0000u);
    float l0 = x0 - h0, l1 = x1 - h1;
    asm("cvt.rn.bf16x2.f32 %0, %1, %2;" : "=r"(lo) : "f"(l1), "f"(l0));
    hi = h;
}
// ldmatrix address for the 4-tile layout used by both A and B(trans)
__device__ __forceinline__ uint32_t ldm_addr(uint32_t base, int row0, int colbyte0, int lane) {
    int grp = lane >> 3, lr = lane & 7;
    uint32_t off = (uint32_t)((row0 + lr + (grp & 1) * 8) * 128 + colbyte0 + (grp >> 1) * 16);
    return base + sw128(off);
}

__device__ __forceinline__ unsigned f2ord(float f) {
    unsigned u = __float_as_uint(f);
    return (u & 0x80000000u) ? ~u : (u | 0x80000000u);
}
__device__ __forceinline__ float ord2f(unsigned u) {
    u = (u & 0x80000000u) ? (u ^ 0x80000000u) : ~u;
    return __uint_as_float(u);
}
__device__ __forceinline__ float sigmoidf_(float v) {
    return 1.0f / (1.0f + expf(-v));
}

// ---------------- threshold: parallel exact rank-select ----------------------
__global__ void kzero() {
    g_hist16[blockIdx.x * 1024 + threadIdx.x] = 0;
}
__global__ void khist16(const float* __restrict__ ap) {
    unsigned u = f2ord(ap[blockIdx.x * 1024 + threadIdx.x]);
    atomicAdd(&g_hist16[u >> 16], 1u);
}
__global__ void kselect(const float* __restrict__ ap) {
    __shared__ unsigned psum[1024];
    __shared__ unsigned s_bin, s_r, cnt;
    __shared__ unsigned cand[8192];
    int tid = threadIdx.x;
    unsigned s = 0;
#pragma unroll 8
    for (int i = 0; i < 64; i++) s += g_hist16[tid * 64 + i];
    psum[tid] = s;
    if (tid == 0) cnt = 0;
    __syncthreads();
    if (tid == 0) {
        unsigned cum = 0;
        int seg = 0;
        for (; seg < 1024; seg++) {
            if (cum + psum[seg] > (unsigned)RANK_K) break;
            cum += psum[seg];
        }
        unsigned r = RANK_K - cum;
        unsigned b = seg * 64;
        for (int i = 0; i < 64; i++) {
            unsigned h = g_hist16[seg * 64 + i];
            if (r < h) { b = seg * 64 + i; break; }
            r -= h;
        }
        s_bin = b;
        s_r = r;
    }
    __syncthreads();
    unsigned b = s_bin;
    for (int i = tid; i < 65536; i += 1024) {
        unsigned u = f2ord(ap[i]);
        if ((u >> 16) == b) {
            unsigned p = atomicAdd(&cnt, 1u);
            if (p < 8192) cand[p] = u;
        }
    }
    __syncthreads();
    unsigned c = min(cnt, 8192u);
    unsigned r = s_r;
    for (unsigned i = tid; i < c; i += 1024) {
        unsigned u = cand[i];
        unsigned less = 0, eq = 0;
        for (unsigned j = 0; j < c; j++) {
            less += (cand[j] < u) ? 1u : 0u;
            eq += (cand[j] == u) ? 1u : 0u;
        }
        if (less <= r && r < less + eq) g_thr = sigmoidf_(ord2f(u));
    }
}

// ---------------- kernel 2: adjacency build + output -------------------------
__global__ void kadj(const float* __restrict__ adj_param, float* __restrict__ out_adj) {
    int idx = blockIdx.x * blockDim.x + threadIdx.x;
    int i = idx >> 8, j = idx & 255;
    float s = sigmoidf_(adj_param[idx]);
    float a = (s > g_thr && i != j) ? s : 0.0f;
    g_adj[idx] = a;
    if (out_adj) out_adj[idx] = a;
}

// ---------------- kernel 3: effW1 = 0.5*(I + adj^T) @ G ----------------------
__global__ void keff(const float* __restrict__ gpW1) {
    __shared__ float adjs[32][36];
    __shared__ float Gs[32][132];
    int tx = threadIdx.x & 31;
    int ty = threadIdx.x >> 5;
    int de0 = blockIdx.x * 128;
    int j0 = blockIdx.y * 32;
    float acc[4][4] = {};
    for (int i0 = 0; i0 < NN; i0 += 32) {
        for (int l = threadIdx.x; l < 32 * 32; l += 256) {
            int ii = l >> 5, jj = l & 31;
            adjs[ii][jj] = g_adj[(i0 + ii) * NN + j0 + jj];
        }
        for (int l = threadIdx.x; l < 32 * 32; l += 256) {
            int ii = l >> 5, dq = (l & 31) * 4;
            float4 v = *reinterpret_cast<const float4*>(&gpW1[(size_t)(i0 + ii) * 4096 + de0 + dq]);
            *reinterpret_cast<float4*>(&Gs[ii][dq]) = v;
        }
        __syncthreads();
#pragma unroll
        for (int k = 0; k < 32; k++) {
            float4 a4 = *reinterpret_cast<const float4*>(&adjs[k][ty * 4]);
            float4 g4 = *reinterpret_cast<const float4*>(&Gs[k][tx * 4]);
            float av[4] = {a4.x, a4.y, a4.z, a4.w};
            float gv[4] = {g4.x, g4.y, g4.z, g4.w};
#pragma unroll
            for (int jj = 0; jj < 4; jj++)
#pragma unroll
                for (int dq = 0; dq < 4; dq++) acc[jj][dq] += av[jj] * gv[dq];
        }
        __syncthreads();
    }
#pragma unroll
    for (int jj = 0; jj < 4; jj++) {
        int j = j0 + ty * 4 + jj;
        int de = de0 + tx * 4;
        float4 gd = *reinterpret_cast<const float4*>(&gpW1[(size_t)j * 4096 + de]);
        float4 o;
        o.x = 0.5f * (gd.x + acc[jj][0]);
        o.y = 0.5f * (gd.y + acc[jj][1]);
        o.z = 0.5f * (gd.z + acc[jj][2]);
        o.w = 0.5f * (gd.w + acc[jj][3]);
        *reinterpret_cast<float4*>(&g_eff[(size_t)j * 4096 + de]) = o;
    }
}

// ---------------- bf16x3 GEMM: acc += X[128x64] @ W[64x64] -------------------
// 4 warps: warp w handles rows 32w..32w+31 (two m16 tiles), all 64 cols.
__device__ __forceinline__ void wgemm(uint32_t sb, int w, int lane, float acc[2][8][4]) {
#pragma unroll
    for (int pass = 0; pass < 3; pass++) {
        uint32_t ab = sb + (pass == 2 ? SM_XLO : SM_XHI);
        uint32_t bb = sb + (pass == 1 ? SM_WLO : SM_WHI);
#pragma unroll
        for (int ks = 0; ks < 4; ks++) {
            uint32_t a[2][4];
#pragma unroll
            for (int mt = 0; mt < 2; mt++)
                ldm_x4(a[mt], ldm_addr(ab, 32 * w + 16 * mt, 32 * ks, lane));
            uint32_t b[8][2];
#pragma unroll
            for (int p = 0; p < 4; p++) {
                uint32_t r[4];
                ldm_x4_t(r, ldm_addr(bb, 16 * ks, 32 * p, lane));
                b[2 * p][0] = r[0]; b[2 * p][1] = r[1];
                b[2 * p + 1][0] = r[2]; b[2 * p + 1][1] = r[3];
            }
#pragma unroll
            for (int mt = 0; mt < 2; mt++)
#pragma unroll
                for (int nt = 0; nt < 8; nt++)
                    mma16816(acc[mt][nt], a[mt], b[nt]);
        }
    }
}

// fill W tile (64x64 f32 row-major) into WHI/WLO (swizzled bf16)
__device__ __forceinline__ void fillW(char* smem, const float* __restrict__ Wp, int tid) {
#pragma unroll
    for (int it = 0; it < 16; it++) {
        int l = tid + it * 128;          // pair index 0..2047
        int k = l >> 5, cp = l & 31;
        float2 v = *reinterpret_cast<const float2*>(&Wp[k * 64 + 2 * cp]);
        uint32_t hi, lo;
        split2(v.x, v.y, hi, lo);
        uint32_t off = sw128((uint32_t)(k * 128 + cp * 4));
        *reinterpret_cast<uint32_t*>(smem + SM_WHI + off) = hi;
        *reinterpret_cast<uint32_t*>(smem + SM_WLO + off) = lo;
    }
}

// epilogue: X <- (acc + bias) [relu], split into XHI/XLO (warp-private rows)
__device__ __forceinline__ void epilogue(char* smem, const float acc[2][8][4],
                                         const float* __restrict__ bias, bool relu,
                                         int w, int g, int tq) {
#pragma unroll
    for (int mt = 0; mt < 2; mt++) {
#pragma unroll
        for (int nt = 0; nt < 8; nt++) {
            int col = 8 * nt + 2 * tq;
            float2 bv = *reinterpret_cast<const float2*>(&bias[col]);
            float x0 = acc[mt][nt][0] + bv.x, x1 = acc[mt][nt][1] + bv.y;
            float x2 = acc[mt][nt][2] + bv.x, x3 = acc[mt][nt][3] + bv.y;
            if (relu) {
                x0 = fmaxf(x0, 0.0f); x1 = fmaxf(x1, 0.0f);
                x2 = fmaxf(x2, 0.0f); x3 = fmaxf(x3, 0.0f);
            }
            int row = 32 * w + 16 * mt + g;
            uint32_t hi, lo;
            split2(x0, x1, hi, lo);
            uint32_t off = sw128((uint32_t)(row * 128 + col * 2));
            *reinterpret_cast<uint32_t*>(smem + SM_XHI + off) = hi;
            *reinterpret_cast<uint32_t*>(smem + SM_XLO + off) = lo;
            split2(x2, x3, hi, lo);
            off = sw128((uint32_t)((row + 8) * 128 + col * 2));
            *reinterpret_cast<uint32_t*>(smem + SM_XHI + off) = hi;
            *reinterpret_cast<uint32_t*>(smem + SM_XLO + off) = lo;
        }
    }
}

// ---------------- fused tensor-core kernel (legacy mma.sync) -----------------
// Block (bx, by): rows [bx*128,+128), nodes [by*8,+8). 128 threads, 4 warps.
__global__ void __launch_bounds__(128, 3) kfused_mma(
    const float* __restrict__ x, const float* __restrict__ W1,
    const float* __restrict__ b1, const float* __restrict__ W2,
    const float* __restrict__ b2) {
    extern __shared__ char smem[];
    uint32_t sb = smem_u32(smem);
    float* bias = reinterpret_cast<float*>(smem + SM_BIAS);   // [0:64)=b1, [64:128)=b2
    int tid = threadIdx.x, w = tid >> 5, lane = tid & 31;
    int g = lane >> 2, tq = lane & 3;
    int b0 = blockIdx.x * 128;
    int n0 = blockIdx.y * 8;

    float acc_g[2][8][4] = {};

    for (int nn = 0; nn < 8; nn++) {
        int n = n0 + nn;
        // ---- fill X (split+swizzle), W1, biases ----
#pragma unroll
        for (int it = 0; it < 32; it++) {
            int l = tid + it * 128;      // pair index 0..4095
            int r = l >> 5, cp = l & 31;
            float2 v = *reinterpret_cast<const float2*>(
                &x[(size_t)(b0 + r) * (NN * DD) + n * DD + 2 * cp]);
            uint32_t hi, lo;
            split2(v.x, v.y, hi, lo);
            uint32_t off = sw128((uint32_t)(r * 128 + cp * 4));
            *reinterpret_cast<uint32_t*>(smem + SM_XHI + off) = hi;
            *reinterpret_cast<uint32_t*>(smem + SM_XLO + off) = lo;
        }
        fillW(smem, W1 + (size_t)n * 4096, tid);
        if (tid < 64) bias[tid] = b1[n * DD + tid];
        else bias[tid] = b2[n * DD + tid - 64];
        __syncthreads();

        // ---- layer 1 ----
        {
            float acc[2][8][4] = {};
            wgemm(sb, w, lane, acc);
            __syncthreads();
            epilogue(smem, acc, bias, true, w, g, tq);     // h = relu(.+b1)
        }
        fillW(smem, W2 + (size_t)n * 4096, tid);
        __syncthreads();

        // ---- layer 2 ----
        {
            float acc[2][8][4] = {};
            wgemm(sb, w, lane, acc);
            __syncthreads();
            epilogue(smem, acc, bias + 64, false, w, g, tq);  // node = .+b2
        }
        fillW(smem, g_eff + (size_t)n * 4096, tid);
        __syncthreads();

        // ---- GEMM3: acc_g += node @ eff[n] ----
        wgemm(sb, w, lane, acc_g);
        __syncthreads();
    }

    // ---- write partials ----
#pragma unroll
    for (int mt = 0; mt < 2; mt++) {
#pragma unroll
        for (int nt = 0; nt < 8; nt++) {
            int row = b0 + 32 * w + 16 * mt + g;
            int col = 8 * nt + 2 * tq;
            size_t base = ((size_t)blockIdx.y * BB + row) * 64 + col;
            float2 o0 = {acc_g[mt][nt][0], acc_g[mt][nt][1]};
            float2 o1 = {acc_g[mt][nt][2], acc_g[mt][nt][3]};
            *reinterpret_cast<float2*>(&g_parts[base]) = o0;
            *reinterpret_cast<float2*>(&g_parts[base + 8 * 64]) = o1;
        }
    }
}

// ---------------- kernel: reduce partials + relu + gpW2 epilogue -------------
__global__ void kfinal(const float* __restrict__ gpb1, const float* __restrict__ gpW2,
                       const float* __restrict__ gpb2, float* __restrict__ out) {
    __shared__ float gs[FB][65];
    __shared__ float w2s[64][33];
    __shared__ float b2s[32];
    int b0 = blockIdx.x * FB;
    for (int l = threadIdx.x; l < FB * 64; l += 256) {
        int r = l >> 6, d = l & 63;
        float s = gpb1[d];
#pragma unroll
        for (int ks = 0; ks < NCHUNK; ks++) s += g_parts[((size_t)ks * BB + b0 + r) * 64 + d];
        gs[r][d] = fmaxf(s, 0.0f);
    }
    for (int l = threadIdx.x; l < 2048; l += 256) {
        int d = l >> 5, h = l & 31;
        w2s[d][h] = gpW2[l];
    }
    if (threadIdx.x < 32) b2s[threadIdx.x] = gpb2[threadIdx.x];
    __syncthreads();
    int h = threadIdx.x & 31, rg = threadIdx.x >> 5;
#pragma unroll
    for (int i = 0; i < FB / 8; i++) {
        int r = rg * (FB / 8) + i;
        float s = b2s[h];
#pragma unroll 16
        for (int d = 0; d < 64; d++) s += gs[r][d] * w2s[d][h];
        out[(size_t)(b0 + r) * 32 + h] = s;
    }
}

// ---------------- launch ------------------------------------------------------
extern "C" void kernel_launch(void* const* d_in, const int* in_sizes, int n_in,
                              void* d_out, int out_size) {
    const float* x         = (const float*)d_in[0];
    const float* adj_param = (const float*)d_in[1];
    const float* W1        = (const float*)d_in[2];
    const float* b1        = (const float*)d_in[3];
    const float* W2        = (const float*)d_in[4];
    const float* b2        = (const float*)d_in[5];
    const float* gpW1      = (const float*)d_in[6];
    const float* gpb1      = (const float*)d_in[7];
    const float* gpW2      = (const float*)d_in[8];
    const float* gpb2      = (const float*)d_in[9];
    float* out = (float*)d_out;
    float* adj_out = (out_size >= 131072) ? (out + BB * 32) : nullptr;

    cudaFuncSetAttribute(kfused_mma, cudaFuncAttributeMaxDynamicSharedMemorySize, SM_TOT);

    kzero<<<64, 1024>>>();
    khist16<<<64, 1024>>>(adj_param);
    kselect<<<1, 1024>>>(adj_param);
    kadj<<<64, 1024>>>(adj_param, adj_out);
    keff<<<dim3(32, 8), 256>>>(gpW1);
    kfused_mma<<<dim3(BB / 128, NCHUNK), 128, SM_TOT>>>(x, W1, b1, W2, b2);
    kfinal<<<BB / FB, 256>>>(gpb1, gpW2, gpb2, out);
}

// round 11
// speedup vs baseline: 1.2572x; 1.2572x over previous
#include <cuda_runtime.h>
#include <math.h>
#include <cstdint>

#define NN 256
#define DD 64
#define BB 2048
#define RANK_K 52428          // int(0.8 * 256 * 256)
#define NCHUNK 32             // node chunks; 8 nodes per chunk
#define FB 16                 // kfinal rows per block

// ---------------- scratch (device globals; no allocation allowed) ------------
__device__ float g_thr;
__device__ float g_adj[NN * NN];
__device__ float g_eff[NN * DD * DD];                  // 4 MB
__device__ float g_parts[(size_t)NCHUNK * BB * DD];    // 16.8 MB
__device__ unsigned g_hist16[65536];

// ---------------- smem map for mma kernel (dynamic) --------------------------
#define SM_XHI  0                        // 128x64 bf16, SW128-swizzled rows of 128B
#define SM_XLO  16384
#define SM_WHI  32768                    // 64x64 bf16 swizzled (8 KB)
#define SM_WLO  40960
#define SM_BIAS 49152                    // 128 floats
#define ST_X0   49664                    // raw f32 staging: X rows 0-63 (16 KB)
#define ST_X1   (ST_X0 + 16384)          // X rows 64-127 (16 KB)
#define ST_W    (ST_X1 + 16384)          // W 64x64 f32 (16 KB)
#define SM_TOT  (ST_W + 16384)           // 98816 B -> 2 CTAs/SM

// ---------------- helpers -----------------------------------------------------
__device__ __forceinline__ uint32_t smem_u32(const void* p) {
    uint32_t a;
    asm("{ .reg .u64 t; cvta.to.shared.u64 t, %1; cvt.u32.u64 %0, t; }" : "=r"(a) : "l"(p));
    return a;
}
__device__ __forceinline__ uint32_t sw128(uint32_t o) { return o ^ ((o >> 3) & 0x70u); }

__device__ __forceinline__ void ldm_x4(uint32_t r[4], uint32_t addr) {
    asm volatile("ldmatrix.sync.aligned.m8n8.x4.shared.b16 {%0,%1,%2,%3}, [%4];"
                 : "=r"(r[0]), "=r"(r[1]), "=r"(r[2]), "=r"(r[3]) : "r"(addr));
}
__device__ __forceinline__ void ldm_x4_t(uint32_t r[4], uint32_t addr) {
    asm volatile("ldmatrix.sync.aligned.m8n8.x4.trans.shared.b16 {%0,%1,%2,%3}, [%4];"
                 : "=r"(r[0]), "=r"(r[1]), "=r"(r[2]), "=r"(r[3]) : "r"(addr));
}
__device__ __forceinline__ void mma16816(float c[4], const uint32_t a[4], const uint32_t b[2]) {
    asm volatile(
        "mma.sync.aligned.m16n8k16.row.col.f32.bf16.bf16.f32 "
        "{%0,%1,%2,%3}, {%4,%5,%6,%7}, {%8,%9}, {%0,%1,%2,%3};"
        : "+f"(c[0]), "+f"(c[1]), "+f"(c[2]), "+f"(c[3])
        : "r"(a[0]), "r"(a[1]), "r"(a[2]), "r"(a[3]), "r"(b[0]), "r"(b[1]));
}
__device__ __forceinline__ void split2(float x0, float x1, uint32_t& hi, uint32_t& lo) {
    uint32_t h;
    asm("cvt.rn.bf16x2.f32 %0, %1, %2;" : "=r"(h) : "f"(x1), "f"(x0));
    float h0 = __uint_as_float(h << 16);
    float h1 = __uint_as_float(h & 0xffff0000u);
    float l0 = x0 - h0, l1 = x1 - h1;
    asm("cvt.rn.bf16x2.f32 %0, %1, %2;" : "=r"(lo) : "f"(l1), "f"(l0));
    hi = h;
}
__device__ __forceinline__ uint32_t ldm_addr(uint32_t base, int row0, int colbyte0, int lane) {
    int grp = lane >> 3, lr = lane & 7;
    uint32_t off = (uint32_t)((row0 + lr + (grp & 1) * 8) * 128 + colbyte0 + (grp >> 1) * 16);
    return base + sw128(off);
}
__device__ __forceinline__ void cpa16(uint32_t dst, const float* src) {
    asm volatile("cp.async.cg.shared.global [%0], [%1], 16;" :: "r"(dst), "l"(src));
}
#define CPA_COMMIT() asm volatile("cp.async.commit_group;" ::: "memory")
#define CPA_WAIT0()  asm volatile("cp.async.wait_group 0;" ::: "memory")
#define CPA_WAIT1()  asm volatile("cp.async.wait_group 1;" ::: "memory")

__device__ __forceinline__ unsigned f2ord(float f) {
    unsigned u = __float_as_uint(f);
    return (u & 0x80000000u) ? ~u : (u | 0x80000000u);
}
__device__ __forceinline__ float ord2f(unsigned u) {
    u = (u & 0x80000000u) ? (u ^ 0x80000000u) : ~u;
    return __uint_as_float(u);
}
__device__ __forceinline__ float sigmoidf_(float v) {
    return 1.0f / (1.0f + expf(-v));
}

// ---------------- threshold: parallel exact rank-select ----------------------
__global__ void kzero() {
    g_hist16[blockIdx.x * 1024 + threadIdx.x] = 0;
}
__global__ void khist16(const float* __restrict__ ap) {
    unsigned u = f2ord(ap[blockIdx.x * 1024 + threadIdx.x]);
    atomicAdd(&g_hist16[u >> 16], 1u);
}
__global__ void kselect(const float* __restrict__ ap) {
    __shared__ unsigned psum[1024];
    __shared__ unsigned s_bin, s_r, cnt;
    __shared__ unsigned cand[8192];
    int tid = threadIdx.x;
    unsigned s = 0;
#pragma unroll 8
    for (int i = 0; i < 64; i++) s += g_hist16[tid * 64 + i];
    psum[tid] = s;
    if (tid == 0) cnt = 0;
    __syncthreads();
    if (tid == 0) {
        unsigned cum = 0;
        int seg = 0;
        for (; seg < 1024; seg++) {
            if (cum + psum[seg] > (unsigned)RANK_K) break;
            cum += psum[seg];
        }
        unsigned r = RANK_K - cum;
        unsigned b = seg * 64;
        for (int i = 0; i < 64; i++) {
            unsigned h = g_hist16[seg * 64 + i];
            if (r < h) { b = seg * 64 + i; break; }
            r -= h;
        }
        s_bin = b;
        s_r = r;
    }
    __syncthreads();
    unsigned b = s_bin;
    for (int i = tid; i < 65536; i += 1024) {
        unsigned u = f2ord(ap[i]);
        if ((u >> 16) == b) {
            unsigned p = atomicAdd(&cnt, 1u);
            if (p < 8192) cand[p] = u;
        }
    }
    __syncthreads();
    unsigned c = min(cnt, 8192u);
    unsigned r = s_r;
    for (unsigned i = tid; i < c; i += 1024) {
        unsigned u = cand[i];
        unsigned less = 0, eq = 0;
        for (unsigned j = 0; j < c; j++) {
            less += (cand[j] < u) ? 1u : 0u;
            eq += (cand[j] == u) ? 1u : 0u;
        }
        if (less <= r && r < less + eq) g_thr = sigmoidf_(ord2f(u));
    }
}

// ---------------- kernel 2: adjacency build + output -------------------------
__global__ void kadj(const float* __restrict__ adj_param, float* __restrict__ out_adj) {
    int idx = blockIdx.x * blockDim.x + threadIdx.x;
    int i = idx >> 8, j = idx & 255;
    float s = sigmoidf_(adj_param[idx]);
    float a = (s > g_thr && i != j) ? s : 0.0f;
    g_adj[idx] = a;
    if (out_adj) out_adj[idx] = a;
}

// ---------------- kernel 3: effW1 = 0.5*(I + adj^T) @ G ----------------------
__global__ void keff(const float* __restrict__ gpW1) {
    __shared__ float adjs[32][36];
    __shared__ float Gs[32][132];
    int tx = threadIdx.x & 31;
    int ty = threadIdx.x >> 5;
    int de0 = blockIdx.x * 128;
    int j0 = blockIdx.y * 32;
    float acc[4][4] = {};
    for (int i0 = 0; i0 < NN; i0 += 32) {
        for (int l = threadIdx.x; l < 32 * 32; l += 256) {
            int ii = l >> 5, jj = l & 31;
            adjs[ii][jj] = g_adj[(i0 + ii) * NN + j0 + jj];
        }
        for (int l = threadIdx.x; l < 32 * 32; l += 256) {
            int ii = l >> 5, dq = (l & 31) * 4;
            float4 v = *reinterpret_cast<const float4*>(&gpW1[(size_t)(i0 + ii) * 4096 + de0 + dq]);
            *reinterpret_cast<float4*>(&Gs[ii][dq]) = v;
        }
        __syncthreads();
#pragma unroll
        for (int k = 0; k < 32; k++) {
            float4 a4 = *reinterpret_cast<const float4*>(&adjs[k][ty * 4]);
            float4 g4 = *reinterpret_cast<const float4*>(&Gs[k][tx * 4]);
            float av[4] = {a4.x, a4.y, a4.z, a4.w};
            float gv[4] = {g4.x, g4.y, g4.z, g4.w};
#pragma unroll
            for (int jj = 0; jj < 4; jj++)
#pragma unroll
                for (int dq = 0; dq < 4; dq++) acc[jj][dq] += av[jj] * gv[dq];
        }
        __syncthreads();
    }
#pragma unroll
    for (int jj = 0; jj < 4; jj++) {
        int j = j0 + ty * 4 + jj;
        int de = de0 + tx * 4;
        float4 gd = *reinterpret_cast<const float4*>(&gpW1[(size_t)j * 4096 + de]);
        float4 o;
        o.x = 0.5f * (gd.x + acc[jj][0]);
        o.y = 0.5f * (gd.y + acc[jj][1]);
        o.z = 0.5f * (gd.z + acc[jj][2]);
        o.w = 0.5f * (gd.w + acc[jj][3]);
        *reinterpret_cast<float4*>(&g_eff[(size_t)j * 4096 + de]) = o;
    }
}

// ---------------- bf16x3 GEMM: acc += X[128x64] @ W[64x64] -------------------
// 4 warps: warp w handles rows 32w..32w+31 (two m16 tiles), all 64 cols.
__device__ __forceinline__ void wgemm(uint32_t sb, int w, int lane, float acc[2][8][4]) {
#pragma unroll
    for (int pass = 0; pass < 3; pass++) {
        uint32_t ab = sb + (pass == 2 ? SM_XLO : SM_XHI);
        uint32_t bb = sb + (pass == 1 ? SM_WLO : SM_WHI);
#pragma unroll
        for (int ks = 0; ks < 4; ks++) {
            uint32_t a[2][4];
#pragma unroll
            for (int mt = 0; mt < 2; mt++)
                ldm_x4(a[mt], ldm_addr(ab, 32 * w + 16 * mt, 32 * ks, lane));
            uint32_t b[8][2];
#pragma unroll
            for (int p = 0; p < 4; p++) {
                uint32_t r[4];
                ldm_x4_t(r, ldm_addr(bb, 16 * ks, 32 * p, lane));
                b[2 * p][0] = r[0]; b[2 * p][1] = r[1];
                b[2 * p + 1][0] = r[2]; b[2 * p + 1][1] = r[3];
            }
#pragma unroll
            for (int mt = 0; mt < 2; mt++)
#pragma unroll
                for (int nt = 0; nt < 8; nt++)
                    mma16816(acc[mt][nt], a[mt], b[nt]);
        }
    }
}

// ---- async staging -----------------------------------------------------------
// stage one 64-row half of the X tile (raw f32, contiguous [r*64+c]) via cp.async
__device__ __forceinline__ void stageX(uint32_t sb, uint32_t stoff,
                                       const float* __restrict__ x,
                                       int b0, int n, int half, int tid) {
#pragma unroll
    for (int it = 0; it < 8; it++) {
        int ch = tid + it * 128;          // chunk 0..1023
        int r = ch >> 4, c16 = ch & 15;   // row-in-half, 16B chunk
        cpa16(sb + stoff + (uint32_t)(r * 256 + c16 * 16),
              &x[(size_t)(b0 + half * 64 + r) * (NN * DD) + n * DD + c16 * 4]);
    }
}
// stage a 64x64 f32 weight tile (contiguous) via cp.async
__device__ __forceinline__ void stageW(uint32_t sb, uint32_t stoff,
                                       const float* __restrict__ Wp, int tid) {
#pragma unroll
    for (int it = 0; it < 8; it++) {
        int off = (tid + it * 128) * 16;
        cpa16(sb + stoff + off, (const float*)((const char*)Wp + off));
    }
}
// convert staged X (ST_X0 rows 0-63, ST_X1 rows 64-127) -> XHI/XLO (LDS source)
__device__ __forceinline__ void convX_stage(char* smem, int tid) {
#pragma unroll 4
    for (int it = 0; it < 32; it++) {
        int l = tid + it * 128;          // pair 0..4095
        int r = l >> 5, cp = l & 31;
        const float* st = reinterpret_cast<const float*>(smem + (r < 64 ? ST_X0 : ST_X1));
        float2 v = *reinterpret_cast<const float2*>(&st[(r & 63) * 64 + 2 * cp]);
        uint32_t hi, lo;
        split2(v.x, v.y, hi, lo);
        uint32_t off = sw128((uint32_t)(r * 128 + cp * 4));
        *reinterpret_cast<uint32_t*>(smem + SM_XHI + off) = hi;
        *reinterpret_cast<uint32_t*>(smem + SM_XLO + off) = lo;
    }
}
// convert a staged f32 W tile -> WHI/WLO (LDS source)
__device__ __forceinline__ void fillW_stage(char* smem, int stoff, int tid) {
    const float* stage = reinterpret_cast<const float*>(smem + stoff);
#pragma unroll 4
    for (int it = 0; it < 16; it++) {
        int l = tid + it * 128;          // pair 0..2047
        int k = l >> 5, cp = l & 31;
        float2 v = *reinterpret_cast<const float2*>(&stage[k * 64 + 2 * cp]);
        uint32_t hi, lo;
        split2(v.x, v.y, hi, lo);
        uint32_t off = sw128((uint32_t)(k * 128 + cp * 4));
        *reinterpret_cast<uint32_t*>(smem + SM_WHI + off) = hi;
        *reinterpret_cast<uint32_t*>(smem + SM_WLO + off) = lo;
    }
}

// epilogue: X <- (acc + bias) [relu], split into XHI/XLO (warp-private rows)
__device__ __forceinline__ void epilogue(char* smem, const float acc[2][8][4],
                                         const float* __restrict__ bias, bool relu,
                                         int w, int g, int tq) {
#pragma unroll
    for (int mt = 0; mt < 2; mt++) {
#pragma unroll
        for (int nt = 0; nt < 8; nt++) {
            int col = 8 * nt + 2 * tq;
            float2 bv = *reinterpret_cast<const float2*>(&bias[col]);
            float x0 = acc[mt][nt][0] + bv.x, x1 = acc[mt][nt][1] + bv.y;
            float x2 = acc[mt][nt][2] + bv.x, x3 = acc[mt][nt][3] + bv.y;
            if (relu) {
                x0 = fmaxf(x0, 0.0f); x1 = fmaxf(x1, 0.0f);
                x2 = fmaxf(x2, 0.0f); x3 = fmaxf(x3, 0.0f);
            }
            int row = 32 * w + 16 * mt + g;
            uint32_t hi, lo;
            split2(x0, x1, hi, lo);
            uint32_t off = sw128((uint32_t)(row * 128 + col * 2));
            *reinterpret_cast<uint32_t*>(smem + SM_XHI + off) = hi;
            *reinterpret_cast<uint32_t*>(smem + SM_XLO + off) = lo;
            split2(x2, x3, hi, lo);
            off = sw128((uint32_t)((row + 8) * 128 + col * 2));
            *reinterpret_cast<uint32_t*>(smem + SM_XHI + off) = hi;
            *reinterpret_cast<uint32_t*>(smem + SM_XLO + off) = lo;
        }
    }
}

// ---------------- fused tensor-core kernel (cp.async-hidden fills) -----------
// Block (bx, by): rows [bx*128,+128), nodes [by*8,+8). 128 threads, 4 warps.
__global__ void __launch_bounds__(128, 2) kfused_mma(
    const float* __restrict__ x, const float* __restrict__ W1,
    const float* __restrict__ b1, const float* __restrict__ W2,
    const float* __restrict__ b2) {
    extern __shared__ char smem[];
    uint32_t sb = smem_u32(smem);
    float* bias = reinterpret_cast<float*>(smem + SM_BIAS);   // [0:64)=b1, [64:128)=b2
    int tid = threadIdx.x, w = tid >> 5, lane = tid & 31;
    int g = lane >> 2, tq = lane & 3;
    int b0 = blockIdx.x * 128;
    int n0 = blockIdx.y * 8;

    float acc_g[2][8][4] = {};

    // prologue: stage X(n0) + W1(n0)
    stageX(sb, ST_X0, x, b0, n0, 0, tid);
    stageX(sb, ST_X1, x, b0, n0, 1, tid);
    stageW(sb, ST_W, W1 + (size_t)n0 * 4096, tid);
    CPA_COMMIT();
    CPA_WAIT0();
    __syncthreads();

    for (int nn = 0; nn < 8; nn++) {
        int n = n0 + nn;
        // ---- convert staged X(n) + W1(n); biases (tiny LDG) ----
        convX_stage(smem, tid);
        fillW_stage(smem, ST_W, tid);
        if (tid < 64) bias[tid] = b1[n * DD + tid];
        else bias[tid] = b2[n * DD + tid - 64];
        __syncthreads();

        // prefetch W2(n) -> ST_W [G1], eff(n) -> ST_X0 [G2]
        stageW(sb, ST_W, W2 + (size_t)n * 4096, tid);   CPA_COMMIT();
        stageW(sb, ST_X0, g_eff + (size_t)n * 4096, tid); CPA_COMMIT();

        // ---- layer 1 ----
        {
            float acc[2][8][4] = {};
            wgemm(sb, w, lane, acc);
            CPA_WAIT1();                       // G1 (W2) landed
            __syncthreads();
            epilogue(smem, acc, bias, true, w, g, tq);   // X <- relu(.+b1)
            fillW_stage(smem, ST_W, tid);                // W <- W2
        }
        __syncthreads();

        // prefetch W1(n+1) -> ST_W, Xhi(n+1) -> ST_X1 [G3]
        if (nn < 7) {
            stageW(sb, ST_W, W1 + (size_t)(n + 1) * 4096, tid);
            stageX(sb, ST_X1, x, b0, n + 1, 1, tid);
            CPA_COMMIT();
        }

        // ---- layer 2 ----
        {
            float acc[2][8][4] = {};
            wgemm(sb, w, lane, acc);
            if (nn < 7) { CPA_WAIT1(); } else { CPA_WAIT0(); }   // G2 (eff) landed
            __syncthreads();
            epilogue(smem, acc, bias + 64, false, w, g, tq);     // X <- node
            fillW_stage(smem, ST_X0, tid);                       // W <- eff
        }
        __syncthreads();

        // prefetch Xlo(n+1) -> ST_X0 [G4]
        if (nn < 7) {
            stageX(sb, ST_X0, x, b0, n + 1, 0, tid);
            CPA_COMMIT();
        }

        // ---- GEMM3: acc_g += node @ eff[n] ----
        wgemm(sb, w, lane, acc_g);
        CPA_WAIT0();                          // G3+G4 landed (no-op on last)
        __syncthreads();
    }

    // ---- write partials ----
#pragma unroll
    for (int mt = 0; mt < 2; mt++) {
#pragma unroll
        for (int nt = 0; nt < 8; nt++) {
            int row = b0 + 32 * w + 16 * mt + g;
            int col = 8 * nt + 2 * tq;
            size_t base = ((size_t)blockIdx.y * BB + row) * 64 + col;
            float2 o0 = {acc_g[mt][nt][0], acc_g[mt][nt][1]};
            float2 o1 = {acc_g[mt][nt][2], acc_g[mt][nt][3]};
            *reinterpret_cast<float2*>(&g_parts[base]) = o0;
            *reinterpret_cast<float2*>(&g_parts[base + 8 * 64]) = o1;
        }
    }
}

// ---------------- kernel: reduce partials + relu + gpW2 epilogue -------------
__global__ void kfinal(const float* __restrict__ gpb1, const float* __restrict__ gpW2,
                       const float* __restrict__ gpb2, float* __restrict__ out) {
    __shared__ float gs[FB][65];
    __shared__ float w2s[64][33];
    __shared__ float b2s[32];
    int b0 = blockIdx.x * FB;
    for (int l = threadIdx.x; l < FB * 64; l += 256) {
        int r = l >> 6, d = l & 63;
        float s = gpb1[d];
#pragma unroll
        for (int ks = 0; ks < NCHUNK; ks++) s += g_parts[((size_t)ks * BB + b0 + r) * 64 + d];
        gs[r][d] = fmaxf(s, 0.0f);
    }
    for (int l = threadIdx.x; l < 2048; l += 256) {
        int d = l >> 5, h = l & 31;
        w2s[d][h] = gpW2[l];
    }
    if (threadIdx.x < 32) b2s[threadIdx.x] = gpb2[threadIdx.x];
    __syncthreads();
    int h = threadIdx.x & 31, rg = threadIdx.x >> 5;
#pragma unroll
    for (int i = 0; i < FB / 8; i++) {
        int r = rg * (FB / 8) + i;
        float s = b2s[h];
#pragma unroll 16
        for (int d = 0; d < 64; d++) s += gs[r][d] * w2s[d][h];
        out[(size_t)(b0 + r) * 32 + h] = s;
    }
}

// ---------------- launch ------------------------------------------------------
extern "C" void kernel_launch(void* const* d_in, const int* in_sizes, int n_in,
                              void* d_out, int out_size) {
    const float* x         = (const float*)d_in[0];
    const float* adj_param = (const float*)d_in[1];
    const float* W1        = (const float*)d_in[2];
    const float* b1        = (const float*)d_in[3];
    const float* W2        = (const float*)d_in[4];
    const float* b2        = (const float*)d_in[5];
    const float* gpW1      = (const float*)d_in[6];
    const float* gpb1      = (const float*)d_in[7];
    const float* gpW2      = (const float*)d_in[8];
    const float* gpb2      = (const float*)d_in[9];
    float* out = (float*)d_out;
    float* adj_out = (out_size >= 131072) ? (out + BB * 32) : nullptr;

    cudaFuncSetAttribute(kfused_mma, cudaFuncAttributeMaxDynamicSharedMemorySize, SM_TOT);

    kzero<<<64, 1024>>>();
    khist16<<<64, 1024>>>(adj_param);
    kselect<<<1, 1024>>>(adj_param);
    kadj<<<64, 1024>>>(adj_param, adj_out);
    keff<<<dim3(32, 8), 256>>>(gpW1);
    kfused_mma<<<dim3(BB / 128, NCHUNK), 128, SM_TOT>>>(x, W1, b1, W2, b2);
    kfinal<<<BB / FB, 256>>>(gpb1, gpW2, gpb2, out);
}

// round 12
// speedup vs baseline: 1.3279x; 1.0563x over previous
#include <cuda_runtime.h>
#include <math.h>
#include <cstdint>

#define NN 256
#define DD 64
#define BB 2048
#define RANK_K 52428          // int(0.8 * 256 * 256)
#define NCHUNK 32             // node chunks; 8 nodes per chunk
#define FB 16                 // kfinal rows per block

// ---------------- scratch (device globals; no allocation allowed) ------------
__device__ float g_thr;
__device__ float g_adj[NN * NN];
__device__ float g_eff[NN * DD * DD];                  // 4 MB
__device__ float g_parts[(size_t)NCHUNK * BB * DD];    // 16.8 MB
__device__ unsigned g_hist16[65536];

// ---------------- smem map for mma kernel (dynamic) --------------------------
#define SM_XHI  0                        // 128x64 bf16, SW128-swizzled rows of 128B
#define SM_XLO  16384
#define SM_WHI  32768                    // 64x64 bf16 swizzled (8 KB)
#define SM_WLO  40960
#define SM_BIAS 49152                    // 128 floats
#define ST_X0   49664                    // raw f32 staging: X rows 0-63 (16 KB)
#define ST_X1   (ST_X0 + 16384)          // X rows 64-127 (16 KB)
#define ST_W    (ST_X1 + 16384)          // W 64x64 f32 (16 KB)
#define SM_TOT  (ST_W + 16384)           // 98816 B -> 2 CTAs/SM

// ---------------- helpers -----------------------------------------------------
__device__ __forceinline__ uint32_t smem_u32(const void* p) {
    uint32_t a;
    asm("{ .reg .u64 t; cvta.to.shared.u64 t, %1; cvt.u32.u64 %0, t; }" : "=r"(a) : "l"(p));
    return a;
}
__device__ __forceinline__ uint32_t sw128(uint32_t o) { return o ^ ((o >> 3) & 0x70u); }

__device__ __forceinline__ void ldm_x4(uint32_t r[4], uint32_t addr) {
    asm volatile("ldmatrix.sync.aligned.m8n8.x4.shared.b16 {%0,%1,%2,%3}, [%4];"
                 : "=r"(r[0]), "=r"(r[1]), "=r"(r[2]), "=r"(r[3]) : "r"(addr));
}
__device__ __forceinline__ void ldm_x4_t(uint32_t r[4], uint32_t addr) {
    asm volatile("ldmatrix.sync.aligned.m8n8.x4.trans.shared.b16 {%0,%1,%2,%3}, [%4];"
                 : "=r"(r[0]), "=r"(r[1]), "=r"(r[2]), "=r"(r[3]) : "r"(addr));
}
__device__ __forceinline__ void mma16816(float c[4], const uint32_t a[4], const uint32_t b[2]) {
    asm volatile(
        "mma.sync.aligned.m16n8k16.row.col.f32.bf16.bf16.f32 "
        "{%0,%1,%2,%3}, {%4,%5,%6,%7}, {%8,%9}, {%0,%1,%2,%3};"
        : "+f"(c[0]), "+f"(c[1]), "+f"(c[2]), "+f"(c[3])
        : "r"(a[0]), "r"(a[1]), "r"(a[2]), "r"(a[3]), "r"(b[0]), "r"(b[1]));
}
__device__ __forceinline__ void split2(float x0, float x1, uint32_t& hi, uint32_t& lo) {
    uint32_t h;
    asm("cvt.rn.bf16x2.f32 %0, %1, %2;" : "=r"(h) : "f"(x1), "f"(x0));
    float h0 = __uint_as_float(h << 16);
    float h1 = __uint_as_float(h & 0xffff0000u);
    float l0 = x0 - h0, l1 = x1 - h1;
    asm("cvt.rn.bf16x2.f32 %0, %1, %2;" : "=r"(lo) : "f"(l1), "f"(l0));
    hi = h;
}
__device__ __forceinline__ uint32_t ldm_addr(uint32_t base, int row0, int colbyte0, int lane) {
    int grp = lane >> 3, lr = lane & 7;
    uint32_t off = (uint32_t)((row0 + lr + (grp & 1) * 8) * 128 + colbyte0 + (grp >> 1) * 16);
    return base + sw128(off);
}
__device__ __forceinline__ void cpa16(uint32_t dst, const float* src) {
    asm volatile("cp.async.cg.shared.global [%0], [%1], 16;" :: "r"(dst), "l"(src));
}
#define CPA_COMMIT() asm volatile("cp.async.commit_group;" ::: "memory")
#define CPA_WAIT0()  asm volatile("cp.async.wait_group 0;" ::: "memory")
#define CPA_WAIT1()  asm volatile("cp.async.wait_group 1;" ::: "memory")

__device__ __forceinline__ unsigned f2ord(float f) {
    unsigned u = __float_as_uint(f);
    return (u & 0x80000000u) ? ~u : (u | 0x80000000u);
}
__device__ __forceinline__ float ord2f(unsigned u) {
    u = (u & 0x80000000u) ? (u ^ 0x80000000u) : ~u;
    return __uint_as_float(u);
}
__device__ __forceinline__ float sigmoidf_(float v) {
    return 1.0f / (1.0f + expf(-v));
}

// ---------------- threshold: parallel exact rank-select ----------------------
__global__ void kzero() {
    g_hist16[blockIdx.x * 1024 + threadIdx.x] = 0;
}
__global__ void khist16(const float* __restrict__ ap) {
    unsigned u = f2ord(ap[blockIdx.x * 1024 + threadIdx.x]);
    atomicAdd(&g_hist16[u >> 16], 1u);
}
__global__ void kselect(const float* __restrict__ ap) {
    __shared__ unsigned psum[1024];
    __shared__ unsigned s_bin, s_r, cnt;
    __shared__ unsigned cand[8192];
    int tid = threadIdx.x;
    unsigned s = 0;
#pragma unroll 8
    for (int i = 0; i < 64; i++) s += g_hist16[tid * 64 + i];
    psum[tid] = s;
    if (tid == 0) cnt = 0;
    __syncthreads();
    if (tid == 0) {
        unsigned cum = 0;
        int seg = 0;
        for (; seg < 1024; seg++) {
            if (cum + psum[seg] > (unsigned)RANK_K) break;
            cum += psum[seg];
        }
        unsigned r = RANK_K - cum;
        unsigned b = seg * 64;
        for (int i = 0; i < 64; i++) {
            unsigned h = g_hist16[seg * 64 + i];
            if (r < h) { b = seg * 64 + i; break; }
            r -= h;
        }
        s_bin = b;
        s_r = r;
    }
    __syncthreads();
    unsigned b = s_bin;
    for (int i = tid; i < 65536; i += 1024) {
        unsigned u = f2ord(ap[i]);
        if ((u >> 16) == b) {
            unsigned p = atomicAdd(&cnt, 1u);
            if (p < 8192) cand[p] = u;
        }
    }
    __syncthreads();
    unsigned c = min(cnt, 8192u);
    unsigned r = s_r;
    for (unsigned i = tid; i < c; i += 1024) {
        unsigned u = cand[i];
        unsigned less = 0, eq = 0;
        for (unsigned j = 0; j < c; j++) {
            less += (cand[j] < u) ? 1u : 0u;
            eq += (cand[j] == u) ? 1u : 0u;
        }
        if (less <= r && r < less + eq) g_thr = sigmoidf_(ord2f(u));
    }
}

// ---------------- kernel 2: adjacency build + output -------------------------
__global__ void kadj(const float* __restrict__ adj_param, float* __restrict__ out_adj) {
    int idx = blockIdx.x * blockDim.x + threadIdx.x;
    int i = idx >> 8, j = idx & 255;
    float s = sigmoidf_(adj_param[idx]);
    float a = (s > g_thr && i != j) ? s : 0.0f;
    g_adj[idx] = a;
    if (out_adj) out_adj[idx] = a;
}

// ---------------- kernel 3: effW1 = 0.5*(I + adj^T) @ G ----------------------
__global__ void keff(const float* __restrict__ gpW1) {
    __shared__ float adjs[32][36];
    __shared__ float Gs[32][132];
    int tx = threadIdx.x & 31;
    int ty = threadIdx.x >> 5;
    int de0 = blockIdx.x * 128;
    int j0 = blockIdx.y * 32;
    float acc[4][4] = {};
    for (int i0 = 0; i0 < NN; i0 += 32) {
        for (int l = threadIdx.x; l < 32 * 32; l += 256) {
            int ii = l >> 5, jj = l & 31;
            adjs[ii][jj] = g_adj[(i0 + ii) * NN + j0 + jj];
        }
        for (int l = threadIdx.x; l < 32 * 32; l += 256) {
            int ii = l >> 5, dq = (l & 31) * 4;
            float4 v = *reinterpret_cast<const float4*>(&gpW1[(size_t)(i0 + ii) * 4096 + de0 + dq]);
            *reinterpret_cast<float4*>(&Gs[ii][dq]) = v;
        }
        __syncthreads();
#pragma unroll
        for (int k = 0; k < 32; k++) {
            float4 a4 = *reinterpret_cast<const float4*>(&adjs[k][ty * 4]);
            float4 g4 = *reinterpret_cast<const float4*>(&Gs[k][tx * 4]);
            float av[4] = {a4.x, a4.y, a4.z, a4.w};
            float gv[4] = {g4.x, g4.y, g4.z, g4.w};
#pragma unroll
            for (int jj = 0; jj < 4; jj++)
#pragma unroll
                for (int dq = 0; dq < 4; dq++) acc[jj][dq] += av[jj] * gv[dq];
        }
        __syncthreads();
    }
#pragma unroll
    for (int jj = 0; jj < 4; jj++) {
        int j = j0 + ty * 4 + jj;
        int de = de0 + tx * 4;
        float4 gd = *reinterpret_cast<const float4*>(&gpW1[(size_t)j * 4096 + de]);
        float4 o;
        o.x = 0.5f * (gd.x + acc[jj][0]);
        o.y = 0.5f * (gd.y + acc[jj][1]);
        o.z = 0.5f * (gd.z + acc[jj][2]);
        o.w = 0.5f * (gd.w + acc[jj][3]);
        *reinterpret_cast<float4*>(&g_eff[(size_t)j * 4096 + de]) = o;
    }
}

// ---------------- bf16x3 GEMM, hoisted fragments ------------------------------
// acc += Xhi@Whi + Xhi@Wlo + Xlo@Whi, fragments loaded ONCE per k-step.
// 4 warps: warp w handles rows 32w..32w+31 (two m16 tiles), all 64 cols.
__device__ __forceinline__ void wgemm(uint32_t sb, int w, int lane, float acc[2][8][4]) {
#pragma unroll
    for (int ks = 0; ks < 4; ks++) {
        uint32_t ahi[2][4], alo[2][4];
#pragma unroll
        for (int mt = 0; mt < 2; mt++) {
            ldm_x4(ahi[mt], ldm_addr(sb + SM_XHI, 32 * w + 16 * mt, 32 * ks, lane));
            ldm_x4(alo[mt], ldm_addr(sb + SM_XLO, 32 * w + 16 * mt, 32 * ks, lane));
        }
        uint32_t bhi[8][2], blo[8][2];
#pragma unroll
        for (int p = 0; p < 4; p++) {
            uint32_t r[4];
            ldm_x4_t(r, ldm_addr(sb + SM_WHI, 16 * ks, 32 * p, lane));
            bhi[2 * p][0] = r[0]; bhi[2 * p][1] = r[1];
            bhi[2 * p + 1][0] = r[2]; bhi[2 * p + 1][1] = r[3];
            ldm_x4_t(r, ldm_addr(sb + SM_WLO, 16 * ks, 32 * p, lane));
            blo[2 * p][0] = r[0]; blo[2 * p][1] = r[1];
            blo[2 * p + 1][0] = r[2]; blo[2 * p + 1][1] = r[3];
        }
#pragma unroll
        for (int mt = 0; mt < 2; mt++)
#pragma unroll
            for (int nt = 0; nt < 8; nt++) {
                mma16816(acc[mt][nt], ahi[mt], bhi[nt]);
                mma16816(acc[mt][nt], ahi[mt], blo[nt]);
                mma16816(acc[mt][nt], alo[mt], bhi[nt]);
            }
    }
}

// ---- async staging -----------------------------------------------------------
__device__ __forceinline__ void stageX(uint32_t sb, uint32_t stoff,
                                       const float* __restrict__ x,
                                       int b0, int n, int half, int tid) {
#pragma unroll
    for (int it = 0; it < 8; it++) {
        int ch = tid + it * 128;          // chunk 0..1023
        int r = ch >> 4, c16 = ch & 15;   // row-in-half, 16B chunk
        cpa16(sb + stoff + (uint32_t)(r * 256 + c16 * 16),
              &x[(size_t)(b0 + half * 64 + r) * (NN * DD) + n * DD + c16 * 4]);
    }
}
__device__ __forceinline__ void stageW(uint32_t sb, uint32_t stoff,
                                       const float* __restrict__ Wp, int tid) {
#pragma unroll
    for (int it = 0; it < 8; it++) {
        int off = (tid + it * 128) * 16;
        cpa16(sb + stoff + off, (const float*)((const char*)Wp + off));
    }
}
__device__ __forceinline__ void convX_stage(char* smem, int tid) {
#pragma unroll 4
    for (int it = 0; it < 32; it++) {
        int l = tid + it * 128;          // pair 0..4095
        int r = l >> 5, cp = l & 31;
        const float* st = reinterpret_cast<const float*>(smem + (r < 64 ? ST_X0 : ST_X1));
        float2 v = *reinterpret_cast<const float2*>(&st[(r & 63) * 64 + 2 * cp]);
        uint32_t hi, lo;
        split2(v.x, v.y, hi, lo);
        uint32_t off = sw128((uint32_t)(r * 128 + cp * 4));
        *reinterpret_cast<uint32_t*>(smem + SM_XHI + off) = hi;
        *reinterpret_cast<uint32_t*>(smem + SM_XLO + off) = lo;
    }
}
__device__ __forceinline__ void fillW_stage(char* smem, int stoff, int tid) {
    const float* stage = reinterpret_cast<const float*>(smem + stoff);
#pragma unroll 4
    for (int it = 0; it < 16; it++) {
        int l = tid + it * 128;          // pair 0..2047
        int k = l >> 5, cp = l & 31;
        float2 v = *reinterpret_cast<const float2*>(&stage[k * 64 + 2 * cp]);
        uint32_t hi, lo;
        split2(v.x, v.y, hi, lo);
        uint32_t off = sw128((uint32_t)(k * 128 + cp * 4));
        *reinterpret_cast<uint32_t*>(smem + SM_WHI + off) = hi;
        *reinterpret_cast<uint32_t*>(smem + SM_WLO + off) = lo;
    }
}

// epilogue: X <- (acc + bias) [relu], split into XHI/XLO (warp-private rows)
__device__ __forceinline__ void epilogue(char* smem, const float acc[2][8][4],
                                         const float* __restrict__ bias, bool relu,
                                         int w, int g, int tq) {
#pragma unroll
    for (int mt = 0; mt < 2; mt++) {
#pragma unroll
        for (int nt = 0; nt < 8; nt++) {
            int col = 8 * nt + 2 * tq;
            float2 bv = *reinterpret_cast<const float2*>(&bias[col]);
            float x0 = acc[mt][nt][0] + bv.x, x1 = acc[mt][nt][1] + bv.y;
            float x2 = acc[mt][nt][2] + bv.x, x3 = acc[mt][nt][3] + bv.y;
            if (relu) {
                x0 = fmaxf(x0, 0.0f); x1 = fmaxf(x1, 0.0f);
                x2 = fmaxf(x2, 0.0f); x3 = fmaxf(x3, 0.0f);
            }
            int row = 32 * w + 16 * mt + g;
            uint32_t hi, lo;
            split2(x0, x1, hi, lo);
            uint32_t off = sw128((uint32_t)(row * 128 + col * 2));
            *reinterpret_cast<uint32_t*>(smem + SM_XHI + off) = hi;
            *reinterpret_cast<uint32_t*>(smem + SM_XLO + off) = lo;
            split2(x2, x3, hi, lo);
            off = sw128((uint32_t)((row + 8) * 128 + col * 2));
            *reinterpret_cast<uint32_t*>(smem + SM_XHI + off) = hi;
            *reinterpret_cast<uint32_t*>(smem + SM_XLO + off) = lo;
        }
    }
}

// ---------------- fused tensor-core kernel (cp.async-hidden fills) -----------
// Block (bx, by): rows [bx*128,+128), nodes [by*8,+8). 128 threads, 4 warps.
__global__ void __launch_bounds__(128, 2) kfused_mma(
    const float* __restrict__ x, const float* __restrict__ W1,
    const float* __restrict__ b1, const float* __restrict__ W2,
    const float* __restrict__ b2) {
    extern __shared__ char smem[];
    uint32_t sb = smem_u32(smem);
    float* bias = reinterpret_cast<float*>(smem + SM_BIAS);   // [0:64)=b1, [64:128)=b2
    int tid = threadIdx.x, w = tid >> 5, lane = tid & 31;
    int g = lane >> 2, tq = lane & 3;
    int b0 = blockIdx.x * 128;
    int n0 = blockIdx.y * 8;

    float acc_g[2][8][4] = {};

    // prologue: stage X(n0) + W1(n0)
    stageX(sb, ST_X0, x, b0, n0, 0, tid);
    stageX(sb, ST_X1, x, b0, n0, 1, tid);
    stageW(sb, ST_W, W1 + (size_t)n0 * 4096, tid);
    CPA_COMMIT();
    CPA_WAIT0();
    __syncthreads();

    for (int nn = 0; nn < 8; nn++) {
        int n = n0 + nn;
        // ---- convert staged X(n) + W1(n); biases (tiny LDG) ----
        convX_stage(smem, tid);
        fillW_stage(smem, ST_W, tid);
        if (tid < 64) bias[tid] = b1[n * DD + tid];
        else bias[tid] = b2[n * DD + tid - 64];
        __syncthreads();

        // prefetch W2(n) -> ST_W [G1], eff(n) -> ST_X0 [G2]
        stageW(sb, ST_W, W2 + (size_t)n * 4096, tid);   CPA_COMMIT();
        stageW(sb, ST_X0, g_eff + (size_t)n * 4096, tid); CPA_COMMIT();

        // ---- layer 1 ----
        {
            float acc[2][8][4] = {};
            wgemm(sb, w, lane, acc);
            CPA_WAIT1();                       // G1 (W2) landed
            __syncthreads();
            epilogue(smem, acc, bias, true, w, g, tq);   // X <- relu(.+b1)
            fillW_stage(smem, ST_W, tid);                // W <- W2
        }
        __syncthreads();

        // prefetch W1(n+1) -> ST_W, Xhi(n+1) -> ST_X1 [G3]
        if (nn < 7) {
            stageW(sb, ST_W, W1 + (size_t)(n + 1) * 4096, tid);
            stageX(sb, ST_X1, x, b0, n + 1, 1, tid);
            CPA_COMMIT();
        }

        // ---- layer 2 ----
        {
            float acc[2][8][4] = {};
            wgemm(sb, w, lane, acc);
            if (nn < 7) { CPA_WAIT1(); } else { CPA_WAIT0(); }   // G2 (eff) landed
            __syncthreads();
            epilogue(smem, acc, bias + 64, false, w, g, tq);     // X <- node
            fillW_stage(smem, ST_X0, tid);                       // W <- eff
        }
        __syncthreads();

        // prefetch Xlo(n+1) -> ST_X0 [G4]
        if (nn < 7) {
            stageX(sb, ST_X0, x, b0, n + 1, 0, tid);
            CPA_COMMIT();
        }

        // ---- GEMM3: acc_g += node @ eff[n] ----
        wgemm(sb, w, lane, acc_g);
        CPA_WAIT0();                          // G3+G4 landed (no-op on last)
        __syncthreads();
    }

    // ---- write partials ----
#pragma unroll
    for (int mt = 0; mt < 2; mt++) {
#pragma unroll
        for (int nt = 0; nt < 8; nt++) {
            int row = b0 + 32 * w + 16 * mt + g;
            int col = 8 * nt + 2 * tq;
            size_t base = ((size_t)blockIdx.y * BB + row) * 64 + col;
            float2 o0 = {acc_g[mt][nt][0], acc_g[mt][nt][1]};
            float2 o1 = {acc_g[mt][nt][2], acc_g[mt][nt][3]};
            *reinterpret_cast<float2*>(&g_parts[base]) = o0;
            *reinterpret_cast<float2*>(&g_parts[base + 8 * 64]) = o1;
        }
    }
}

// ---------------- kernel: reduce partials + relu + gpW2 epilogue -------------
__global__ void kfinal(const float* __restrict__ gpb1, const float* __restrict__ gpW2,
                       const float* __restrict__ gpb2, float* __restrict__ out) {
    __shared__ float gs[FB][65];
    __shared__ float w2s[64][33];
    __shared__ float b2s[32];
    int b0 = blockIdx.x * FB;
    for (int l = threadIdx.x; l < FB * 64; l += 256) {
        int r = l >> 6, d = l & 63;
        float s = gpb1[d];
#pragma unroll
        for (int ks = 0; ks < NCHUNK; ks++) s += g_parts[((size_t)ks * BB + b0 + r) * 64 + d];
        gs[r][d] = fmaxf(s, 0.0f);
    }
    for (int l = threadIdx.x; l < 2048; l += 256) {
        int d = l >> 5, h = l & 31;
        w2s[d][h] = gpW2[l];
    }
    if (threadIdx.x < 32) b2s[threadIdx.x] = gpb2[threadIdx.x];
    __syncthreads();
    int h = threadIdx.x & 31, rg = threadIdx.x >> 5;
#pragma unroll
    for (int i = 0; i < FB / 8; i++) {
        int r = rg * (FB / 8) + i;
        float s = b2s[h];
#pragma unroll 16
        for (int d = 0; d < 64; d++) s += gs[r][d] * w2s[d][h];
        out[(size_t)(b0 + r) * 32 + h] = s;
    }
}

// ---------------- launch ------------------------------------------------------
extern "C" void kernel_launch(void* const* d_in, const int* in_sizes, int n_in,
                              void* d_out, int out_size) {
    const float* x         = (const float*)d_in[0];
    const float* adj_param = (const float*)d_in[1];
    const float* W1        = (const float*)d_in[2];
    const float* b1        = (const float*)d_in[3];
    const float* W2        = (const float*)d_in[4];
    const float* b2        = (const float*)d_in[5];
    const float* gpW1      = (const float*)d_in[6];
    const float* gpb1      = (const float*)d_in[7];
    const float* gpW2      = (const float*)d_in[8];
    const float* gpb2      = (const float*)d_in[9];
    float* out = (float*)d_out;
    float* adj_out = (out_size >= 131072) ? (out + BB * 32) : nullptr;

    cudaFuncSetAttribute(kfused_mma, cudaFuncAttributeMaxDynamicSharedMemorySize, SM_TOT);

    kzero<<<64, 1024>>>();
    khist16<<<64, 1024>>>(adj_param);
    kselect<<<1, 1024>>>(adj_param);
    kadj<<<64, 1024>>>(adj_param, adj_out);
    keff<<<dim3(32, 8), 256>>>(gpW1);
    kfused_mma<<<dim3(BB / 128, NCHUNK), 128, SM_TOT>>>(x, W1, b1, W2, b2);
    kfinal<<<BB / FB, 256>>>(gpb1, gpW2, gpb2, out);
}

// round 13
// speedup vs baseline: 1.4402x; 1.0846x over previous
#include <cuda_runtime.h>
#include <math.h>
#include <cstdint>

#define NN 256
#define DD 64
#define BB 2048
#define RANK_K 52428          // int(0.8 * 256 * 256)
#define NCHUNK 32             // node chunks; 8 nodes per chunk
#define FB 16                 // kfinal rows per block

// ---------------- scratch (device globals; no allocation allowed) ------------
__device__ float g_thr;
__device__ float g_adj[NN * NN];
__device__ float g_eff[NN * DD * DD];                  // 4 MB
__device__ float g_parts[(size_t)NCHUNK * BB * DD];    // 16.8 MB
__device__ unsigned g_hist16[65536];

// ---------------- smem map for mma kernel (dynamic) --------------------------
#define SM_XHI  0                        // 128x64 bf16, SW128-swizzled rows of 128B
#define SM_XLO  16384
#define SM_WHI  32768                    // 64x64 bf16 swizzled (8 KB)
#define SM_WLO  40960
#define SM_BIAS 49152                    // 128 floats
#define ST_X0   49664                    // raw f32 staging: X rows 0-63 (16 KB)
#define ST_X1   (ST_X0 + 16384)          // X rows 64-127 (16 KB)
#define ST_W    (ST_X1 + 16384)          // W 64x64 f32 (16 KB)
#define SM_TOT  (ST_W + 16384)           // 98816 B -> 2 CTAs/SM

// ---------------- helpers -----------------------------------------------------
__device__ __forceinline__ uint32_t smem_u32(const void* p) {
    uint32_t a;
    asm("{ .reg .u64 t; cvta.to.shared.u64 t, %1; cvt.u32.u64 %0, t; }" : "=r"(a) : "l"(p));
    return a;
}
__device__ __forceinline__ uint32_t sw128(uint32_t o) { return o ^ ((o >> 3) & 0x70u); }

__device__ __forceinline__ void ldm_x4(uint32_t r[4], uint32_t addr) {
    asm volatile("ldmatrix.sync.aligned.m8n8.x4.shared.b16 {%0,%1,%2,%3}, [%4];"
                 : "=r"(r[0]), "=r"(r[1]), "=r"(r[2]), "=r"(r[3]) : "r"(addr));
}
__device__ __forceinline__ void ldm_x4_t(uint32_t r[4], uint32_t addr) {
    asm volatile("ldmatrix.sync.aligned.m8n8.x4.trans.shared.b16 {%0,%1,%2,%3}, [%4];"
                 : "=r"(r[0]), "=r"(r[1]), "=r"(r[2]), "=r"(r[3]) : "r"(addr));
}
__device__ __forceinline__ void mma16816(float c[4], const uint32_t a[4], const uint32_t b[2]) {
    asm volatile(
        "mma.sync.aligned.m16n8k16.row.col.f32.bf16.bf16.f32 "
        "{%0,%1,%2,%3}, {%4,%5,%6,%7}, {%8,%9}, {%0,%1,%2,%3};"
        : "+f"(c[0]), "+f"(c[1]), "+f"(c[2]), "+f"(c[3])
        : "r"(a[0]), "r"(a[1]), "r"(a[2]), "r"(a[3]), "r"(b[0]), "r"(b[1]));
}
__device__ __forceinline__ void split2(float x0, float x1, uint32_t& hi, uint32_t& lo) {
    uint32_t h;
    asm("cvt.rn.bf16x2.f32 %0, %1, %2;" : "=r"(h) : "f"(x1), "f"(x0));
    float h0 = __uint_as_float(h << 16);
    float h1 = __uint_as_float(h & 0xffff0000u);
    float l0 = x0 - h0, l1 = x1 - h1;
    asm("cvt.rn.bf16x2.f32 %0, %1, %2;" : "=r"(lo) : "f"(l1), "f"(l0));
    hi = h;
}
__device__ __forceinline__ uint32_t ldm_addr(uint32_t base, int row0, int colbyte0, int lane) {
    int grp = lane >> 3, lr = lane & 7;
    uint32_t off = (uint32_t)((row0 + lr + (grp & 1) * 8) * 128 + colbyte0 + (grp >> 1) * 16);
    return base + sw128(off);
}
__device__ __forceinline__ void cpa16(uint32_t dst, const float* src) {
    asm volatile("cp.async.cg.shared.global [%0], [%1], 16;" :: "r"(dst), "l"(src));
}
#define CPA_COMMIT() asm volatile("cp.async.commit_group;" ::: "memory")
#define CPA_WAIT0()  asm volatile("cp.async.wait_group 0;" ::: "memory")
#define CPA_WAIT1()  asm volatile("cp.async.wait_group 1;" ::: "memory")

__device__ __forceinline__ unsigned f2ord(float f) {
    unsigned u = __float_as_uint(f);
    return (u & 0x80000000u) ? ~u : (u | 0x80000000u);
}
__device__ __forceinline__ float ord2f(unsigned u) {
    u = (u & 0x80000000u) ? (u ^ 0x80000000u) : ~u;
    return __uint_as_float(u);
}
__device__ __forceinline__ float sigmoidf_(float v) {
    return 1.0f / (1.0f + expf(-v));
}

// ---------------- threshold: parallel exact rank-select ----------------------
__global__ void kzero() {
    g_hist16[blockIdx.x * 1024 + threadIdx.x] = 0;
}
__global__ void khist16(const float* __restrict__ ap) {
    unsigned u = f2ord(ap[blockIdx.x * 1024 + threadIdx.x]);
    atomicAdd(&g_hist16[u >> 16], 1u);
}
__global__ void kselect(const float* __restrict__ ap) {
    __shared__ unsigned psum[1024];
    __shared__ unsigned s_bin, s_r, cnt;
    __shared__ unsigned cand[8192];
    int tid = threadIdx.x;
    unsigned s = 0;
#pragma unroll 8
    for (int i = 0; i < 64; i++) s += g_hist16[tid * 64 + i];
    psum[tid] = s;
    if (tid == 0) cnt = 0;
    __syncthreads();
    if (tid == 0) {
        unsigned cum = 0;
        int seg = 0;
        for (; seg < 1024; seg++) {
            if (cum + psum[seg] > (unsigned)RANK_K) break;
            cum += psum[seg];
        }
        unsigned r = RANK_K - cum;
        unsigned b = seg * 64;
        for (int i = 0; i < 64; i++) {
            unsigned h = g_hist16[seg * 64 + i];
            if (r < h) { b = seg * 64 + i; break; }
            r -= h;
        }
        s_bin = b;
        s_r = r;
    }
    __syncthreads();
    unsigned b = s_bin;
    for (int i = tid; i < 65536; i += 1024) {
        unsigned u = f2ord(ap[i]);
        if ((u >> 16) == b) {
            unsigned p = atomicAdd(&cnt, 1u);
            if (p < 8192) cand[p] = u;
        }
    }
    __syncthreads();
    unsigned c = min(cnt, 8192u);
    unsigned r = s_r;
    for (unsigned i = tid; i < c; i += 1024) {
        unsigned u = cand[i];
        unsigned less = 0, eq = 0;
        for (unsigned j = 0; j < c; j++) {
            less += (cand[j] < u) ? 1u : 0u;
            eq += (cand[j] == u) ? 1u : 0u;
        }
        if (less <= r && r < less + eq) g_thr = sigmoidf_(ord2f(u));
    }
}

// ---------------- kernel 2: adjacency build + output -------------------------
__global__ void kadj(const float* __restrict__ adj_param, float* __restrict__ out_adj) {
    int idx = blockIdx.x * blockDim.x + threadIdx.x;
    int i = idx >> 8, j = idx & 255;
    float s = sigmoidf_(adj_param[idx]);
    float a = (s > g_thr && i != j) ? s : 0.0f;
    g_adj[idx] = a;
    if (out_adj) out_adj[idx] = a;
}

// ---------------- kernel 3: effW1 = 0.5*(I + adj^T) @ G ----------------------
__global__ void keff(const float* __restrict__ gpW1) {
    __shared__ float adjs[32][36];
    __shared__ float Gs[32][132];
    int tx = threadIdx.x & 31;
    int ty = threadIdx.x >> 5;
    int de0 = blockIdx.x * 128;
    int j0 = blockIdx.y * 32;
    float acc[4][4] = {};
    for (int i0 = 0; i0 < NN; i0 += 32) {
        for (int l = threadIdx.x; l < 32 * 32; l += 256) {
            int ii = l >> 5, jj = l & 31;
            adjs[ii][jj] = g_adj[(i0 + ii) * NN + j0 + jj];
        }
        for (int l = threadIdx.x; l < 32 * 32; l += 256) {
            int ii = l >> 5, dq = (l & 31) * 4;
            float4 v = *reinterpret_cast<const float4*>(&gpW1[(size_t)(i0 + ii) * 4096 + de0 + dq]);
            *reinterpret_cast<float4*>(&Gs[ii][dq]) = v;
        }
        __syncthreads();
#pragma unroll
        for (int k = 0; k < 32; k++) {
            float4 a4 = *reinterpret_cast<const float4*>(&adjs[k][ty * 4]);
            float4 g4 = *reinterpret_cast<const float4*>(&Gs[k][tx * 4]);
            float av[4] = {a4.x, a4.y, a4.z, a4.w};
            float gv[4] = {g4.x, g4.y, g4.z, g4.w};
#pragma unroll
            for (int jj = 0; jj < 4; jj++)
#pragma unroll
                for (int dq = 0; dq < 4; dq++) acc[jj][dq] += av[jj] * gv[dq];
        }
        __syncthreads();
    }
#pragma unroll
    for (int jj = 0; jj < 4; jj++) {
        int j = j0 + ty * 4 + jj;
        int de = de0 + tx * 4;
        float4 gd = *reinterpret_cast<const float4*>(&gpW1[(size_t)j * 4096 + de]);
        float4 o;
        o.x = 0.5f * (gd.x + acc[jj][0]);
        o.y = 0.5f * (gd.y + acc[jj][1]);
        o.z = 0.5f * (gd.z + acc[jj][2]);
        o.w = 0.5f * (gd.w + acc[jj][3]);
        *reinterpret_cast<float4*>(&g_eff[(size_t)j * 4096 + de]) = o;
    }
}

// ---------------- bf16x3 GEMM, hoisted fragments ------------------------------
// acc += Xhi@Whi + Xhi@Wlo + Xlo@Whi, fragments loaded ONCE per k-step.
// 4 warps: warp w handles rows 32w..32w+31 (two m16 tiles), all 64 cols.
__device__ __forceinline__ void wgemm(uint32_t sb, int w, int lane, float acc[2][8][4]) {
#pragma unroll
    for (int ks = 0; ks < 4; ks++) {
        uint32_t ahi[2][4], alo[2][4];
#pragma unroll
        for (int mt = 0; mt < 2; mt++) {
            ldm_x4(ahi[mt], ldm_addr(sb + SM_XHI, 32 * w + 16 * mt, 32 * ks, lane));
            ldm_x4(alo[mt], ldm_addr(sb + SM_XLO, 32 * w + 16 * mt, 32 * ks, lane));
        }
        uint32_t bhi[8][2], blo[8][2];
#pragma unroll
        for (int p = 0; p < 4; p++) {
            uint32_t r[4];
            ldm_x4_t(r, ldm_addr(sb + SM_WHI, 16 * ks, 32 * p, lane));
            bhi[2 * p][0] = r[0]; bhi[2 * p][1] = r[1];
            bhi[2 * p + 1][0] = r[2]; bhi[2 * p + 1][1] = r[3];
            ldm_x4_t(r, ldm_addr(sb + SM_WLO, 16 * ks, 32 * p, lane));
            blo[2 * p][0] = r[0]; blo[2 * p][1] = r[1];
            blo[2 * p + 1][0] = r[2]; blo[2 * p + 1][1] = r[3];
        }
#pragma unroll
        for (int mt = 0; mt < 2; mt++)
#pragma unroll
            for (int nt = 0; nt < 8; nt++) {
                mma16816(acc[mt][nt], ahi[mt], bhi[nt]);
                mma16816(acc[mt][nt], ahi[mt], blo[nt]);
                mma16816(acc[mt][nt], alo[mt], bhi[nt]);
            }
    }
}

// ---- async staging -----------------------------------------------------------
__device__ __forceinline__ void stageX(uint32_t sb, uint32_t stoff,
                                       const float* __restrict__ x,
                                       int b0, int n, int half, int tid) {
#pragma unroll
    for (int it = 0; it < 8; it++) {
        int ch = tid + it * 128;          // chunk 0..1023
        int r = ch >> 4, c16 = ch & 15;   // row-in-half, 16B chunk
        cpa16(sb + stoff + (uint32_t)(r * 256 + c16 * 16),
              &x[(size_t)(b0 + half * 64 + r) * (NN * DD) + n * DD + c16 * 4]);
    }
}
__device__ __forceinline__ void stageW(uint32_t sb, uint32_t stoff,
                                       const float* __restrict__ Wp, int tid) {
#pragma unroll
    for (int it = 0; it < 8; it++) {
        int off = (tid + it * 128) * 16;
        cpa16(sb + stoff + off, (const float*)((const char*)Wp + off));
    }
}

// convert staged X -> XHI/XLO, 4 pairs (16B) per iteration, vectorized LDS/STS
__device__ __forceinline__ void convX_stage(char* smem, int tid) {
#pragma unroll
    for (int it = 0; it < 8; it++) {
        int l = tid + it * 128;          // group 0..1023 (4 pairs each)
        int r = l >> 3, p4 = l & 7;
        const float* st = reinterpret_cast<const float*>(smem + (r < 64 ? ST_X0 : ST_X1));
        const float4* src = reinterpret_cast<const float4*>(&st[(r & 63) * 64 + p4 * 8]);
        float4 v0 = src[0], v1 = src[1];
        uint4 hi, lo;
        split2(v0.x, v0.y, hi.x, lo.x);
        split2(v0.z, v0.w, hi.y, lo.y);
        split2(v1.x, v1.y, hi.z, lo.z);
        split2(v1.z, v1.w, hi.w, lo.w);
        uint32_t off = sw128((uint32_t)(r * 128 + p4 * 16));
        *reinterpret_cast<uint4*>(smem + SM_XHI + off) = hi;
        *reinterpret_cast<uint4*>(smem + SM_XLO + off) = lo;
    }
}
// convert staged f32 W tile -> WHI/WLO, 4 pairs per iteration
__device__ __forceinline__ void fillW_stage(char* smem, int stoff, int tid) {
    const float* stage = reinterpret_cast<const float*>(smem + stoff);
#pragma unroll
    for (int it = 0; it < 4; it++) {
        int l = tid + it * 128;          // group 0..511
        int k = l >> 3, p4 = l & 7;
        const float4* src = reinterpret_cast<const float4*>(&stage[k * 64 + p4 * 8]);
        float4 v0 = src[0], v1 = src[1];
        uint4 hi, lo;
        split2(v0.x, v0.y, hi.x, lo.x);
        split2(v0.z, v0.w, hi.y, lo.y);
        split2(v1.x, v1.y, hi.z, lo.z);
        split2(v1.z, v1.w, hi.w, lo.w);
        uint32_t off = sw128((uint32_t)(k * 128 + p4 * 16));
        *reinterpret_cast<uint4*>(smem + SM_WHI + off) = hi;
        *reinterpret_cast<uint4*>(smem + SM_WLO + off) = lo;
    }
}

// epilogue: X <- (acc + bias) [relu], split into XHI/XLO (warp-private rows)
__device__ __forceinline__ void epilogue(char* smem, const float acc[2][8][4],
                                         const float* __restrict__ bias, bool relu,
                                         int w, int g, int tq) {
#pragma unroll
    for (int mt = 0; mt < 2; mt++) {
#pragma unroll
        for (int nt = 0; nt < 8; nt++) {
            int col = 8 * nt + 2 * tq;
            float2 bv = *reinterpret_cast<const float2*>(&bias[col]);
            float x0 = acc[mt][nt][0] + bv.x, x1 = acc[mt][nt][1] + bv.y;
            float x2 = acc[mt][nt][2] + bv.x, x3 = acc[mt][nt][3] + bv.y;
            if (relu) {
                x0 = fmaxf(x0, 0.0f); x1 = fmaxf(x1, 0.0f);
                x2 = fmaxf(x2, 0.0f); x3 = fmaxf(x3, 0.0f);
            }
            int row = 32 * w + 16 * mt + g;
            uint32_t hi, lo;
            split2(x0, x1, hi, lo);
            uint32_t off = sw128((uint32_t)(row * 128 + col * 2));
            *reinterpret_cast<uint32_t*>(smem + SM_XHI + off) = hi;
            *reinterpret_cast<uint32_t*>(smem + SM_XLO + off) = lo;
            split2(x2, x3, hi, lo);
            off = sw128((uint32_t)((row + 8) * 128 + col * 2));
            *reinterpret_cast<uint32_t*>(smem + SM_XHI + off) = hi;
            *reinterpret_cast<uint32_t*>(smem + SM_XLO + off) = lo;
        }
    }
}

// ---------------- fused tensor-core kernel (cp.async-hidden fills) -----------
// Block (bx, by): rows [bx*128,+128), nodes [by*8,+8). 128 threads, 4 warps.
__global__ void __launch_bounds__(128, 2) kfused_mma(
    const float* __restrict__ x, const float* __restrict__ W1,
    const float* __restrict__ b1, const float* __restrict__ W2,
    const float* __restrict__ b2) {
    extern __shared__ char smem[];
    uint32_t sb = smem_u32(smem);
    float* bias = reinterpret_cast<float*>(smem + SM_BIAS);   // [0:64)=b1, [64:128)=b2
    int tid = threadIdx.x, w = tid >> 5, lane = tid & 31;
    int g = lane >> 2, tq = lane & 3;
    int b0 = blockIdx.x * 128;
    int n0 = blockIdx.y * 8;

    float acc_g[2][8][4] = {};

    // prologue: stage X(n0) + W1(n0)
    stageX(sb, ST_X0, x, b0, n0, 0, tid);
    stageX(sb, ST_X1, x, b0, n0, 1, tid);
    stageW(sb, ST_W, W1 + (size_t)n0 * 4096, tid);
    CPA_COMMIT();
    CPA_WAIT0();
    __syncthreads();

    for (int nn = 0; nn < 8; nn++) {
        int n = n0 + nn;
        // ---- convert staged X(n) + W1(n); biases (tiny LDG) ----
        convX_stage(smem, tid);
        fillW_stage(smem, ST_W, tid);
        if (tid < 64) bias[tid] = b1[n * DD + tid];
        else bias[tid] = b2[n * DD + tid - 64];
        __syncthreads();

        // prefetch W2(n) -> ST_W [G1], eff(n) -> ST_X0 [G2]
        stageW(sb, ST_W, W2 + (size_t)n * 4096, tid);   CPA_COMMIT();
        stageW(sb, ST_X0, g_eff + (size_t)n * 4096, tid); CPA_COMMIT();

        // ---- layer 1 ----
        {
            float acc[2][8][4] = {};
            wgemm(sb, w, lane, acc);
            CPA_WAIT1();                       // G1 (W2) landed
            __syncthreads();
            epilogue(smem, acc, bias, true, w, g, tq);   // X <- relu(.+b1)
            fillW_stage(smem, ST_W, tid);                // W <- W2
        }
        __syncthreads();

        // prefetch W1(n+1) -> ST_W, Xhi(n+1) -> ST_X1 [G3]
        if (nn < 7) {
            stageW(sb, ST_W, W1 + (size_t)(n + 1) * 4096, tid);
            stageX(sb, ST_X1, x, b0, n + 1, 1, tid);
            CPA_COMMIT();
        }

        // ---- layer 2 ----
        {
            float acc[2][8][4] = {};
            wgemm(sb, w, lane, acc);
            if (nn < 7) { CPA_WAIT1(); } else { CPA_WAIT0(); }   // G2 (eff) landed
            __syncthreads();
            epilogue(smem, acc, bias + 64, false, w, g, tq);     // X <- node
            fillW_stage(smem, ST_X0, tid);                       // W <- eff
        }
        __syncthreads();

        // prefetch Xlo(n+1) -> ST_X0 [G4]
        if (nn < 7) {
            stageX(sb, ST_X0, x, b0, n + 1, 0, tid);
            CPA_COMMIT();
        }

        // ---- GEMM3: acc_g += node @ eff[n] ----
        wgemm(sb, w, lane, acc_g);
        CPA_WAIT0();                          // G3+G4 landed (no-op on last)
        __syncthreads();
    }

    // ---- write partials ----
#pragma unroll
    for (int mt = 0; mt < 2; mt++) {
#pragma unroll
        for (int nt = 0; nt < 8; nt++) {
            int row = b0 + 32 * w + 16 * mt + g;
            int col = 8 * nt + 2 * tq;
            size_t base = ((size_t)blockIdx.y * BB + row) * 64 + col;
            float2 o0 = {acc_g[mt][nt][0], acc_g[mt][nt][1]};
            float2 o1 = {acc_g[mt][nt][2], acc_g[mt][nt][3]};
            *reinterpret_cast<float2*>(&g_parts[base]) = o0;
            *reinterpret_cast<float2*>(&g_parts[base + 8 * 64]) = o1;
        }
    }
}

// ---------------- kernel: reduce partials + relu + gpW2 epilogue -------------
__global__ void kfinal(const float* __restrict__ gpb1, const float* __restrict__ gpW2,
                       const float* __restrict__ gpb2, float* __restrict__ out) {
    __shared__ float gs[FB][65];
    __shared__ float w2s[64][33];
    __shared__ float b2s[32];
    int b0 = blockIdx.x * FB;
    for (int l = threadIdx.x; l < FB * 64; l += 256) {
        int r = l >> 6, d = l & 63;
        float s = gpb1[d];
#pragma unroll
        for (int ks = 0; ks < NCHUNK; ks++) s += g_parts[((size_t)ks * BB + b0 + r) * 64 + d];
        gs[r][d] = fmaxf(s, 0.0f);
    }
    for (int l = threadIdx.x; l < 2048; l += 256) {
        int d = l >> 5, h = l & 31;
        w2s[d][h] = gpW2[l];
    }
    if (threadIdx.x < 32) b2s[threadIdx.x] = gpb2[threadIdx.x];
    __syncthreads();
    int h = threadIdx.x & 31, rg = threadIdx.x >> 5;
#pragma unroll
    for (int i = 0; i < FB / 8; i++) {
        int r = rg * (FB / 8) + i;
        float s = b2s[h];
#pragma unroll 16
        for (int d = 0; d < 64; d++) s += gs[r][d] * w2s[d][h];
        out[(size_t)(b0 + r) * 32 + h] = s;
    }
}

// ---------------- launch ------------------------------------------------------
extern "C" void kernel_launch(void* const* d_in, const int* in_sizes, int n_in,
                              void* d_out, int out_size) {
    const float* x         = (const float*)d_in[0];
    const float* adj_param = (const float*)d_in[1];
    const float* W1        = (const float*)d_in[2];
    const float* b1        = (const float*)d_in[3];
    const float* W2        = (const float*)d_in[4];
    const float* b2        = (const float*)d_in[5];
    const float* gpW1      = (const float*)d_in[6];
    const float* gpb1      = (const float*)d_in[7];
    const float* gpW2      = (const float*)d_in[8];
    const float* gpb2      = (const float*)d_in[9];
    float* out = (float*)d_out;
    float* adj_out = (out_size >= 131072) ? (out + BB * 32) : nullptr;

    cudaFuncSetAttribute(kfused_mma, cudaFuncAttributeMaxDynamicSharedMemorySize, SM_TOT);

    kzero<<<64, 1024>>>();
    khist16<<<64, 1024>>>(adj_param);
    kselect<<<1, 1024>>>(adj_param);
    kadj<<<64, 1024>>>(adj_param, adj_out);
    keff<<<dim3(32, 8), 256>>>(gpW1);
    kfused_mma<<<dim3(BB / 128, NCHUNK), 128, SM_TOT>>>(x, W1, b1, W2, b2);
    kfinal<<<BB / FB, 256>>>(gpb1, gpW2, gpb2, out);
}

// round 14
// speedup vs baseline: 1.5129x; 1.0505x over previous
#include <cuda_runtime.h>
#include <math.h>
#include <cstdint>

#define NN 256
#define DD 64
#define BB 2048
#define RANK_K 52428          // int(0.8 * 256 * 256)
#define NCHUNK 32             // node chunks; 8 nodes per chunk
#define FB 16                 // kfinal rows per block

// ---------------- scratch (device globals; no allocation allowed) ------------
__device__ float g_thr;
__device__ float g_adj[NN * NN];
__device__ float g_eff[NN * DD * DD];                  // 4 MB
__device__ float g_parts[(size_t)NCHUNK * BB * DD];    // 16.8 MB
__device__ unsigned g_hist16[65536];
// pre-split swizzled bf16 weights: [which(0=W1,1=W2,2=eff)][node][hi 8KB | lo 8KB]
__device__ char g_wbf[(size_t)3 * NN * 16384];         // 12 MB

// ---------------- smem map for mma kernel (dynamic) --------------------------
#define SM_XHI  0                        // 128x64 bf16, SW128-swizzled rows of 128B
#define SM_XLO  16384
#define SM_WB0  32768                    // W ping buffer: hi 8KB @ +0, lo 8KB @ +8192
#define SM_WB1  49152                    // W pong buffer
#define SM_BIAS 65536                    // 128 floats
#define ST_X0   66048                    // raw f32 staging: X rows 0-63 (16 KB)
#define ST_X1   (ST_X0 + 16384)          // X rows 64-127 (16 KB)
#define SM_TOT  (ST_X1 + 16384)          // 98816 B -> 2 CTAs/SM

// ---------------- helpers -----------------------------------------------------
__device__ __forceinline__ uint32_t smem_u32(const void* p) {
    uint32_t a;
    asm("{ .reg .u64 t; cvta.to.shared.u64 t, %1; cvt.u32.u64 %0, t; }" : "=r"(a) : "l"(p));
    return a;
}
__device__ __forceinline__ uint32_t sw128(uint32_t o) { return o ^ ((o >> 3) & 0x70u); }

__device__ __forceinline__ void ldm_x4(uint32_t r[4], uint32_t addr) {
    asm volatile("ldmatrix.sync.aligned.m8n8.x4.shared.b16 {%0,%1,%2,%3}, [%4];"
                 : "=r"(r[0]), "=r"(r[1]), "=r"(r[2]), "=r"(r[3]) : "r"(addr));
}
__device__ __forceinline__ void ldm_x4_t(uint32_t r[4], uint32_t addr) {
    asm volatile("ldmatrix.sync.aligned.m8n8.x4.trans.shared.b16 {%0,%1,%2,%3}, [%4];"
                 : "=r"(r[0]), "=r"(r[1]), "=r"(r[2]), "=r"(r[3]) : "r"(addr));
}
__device__ __forceinline__ void mma16816(float c[4], const uint32_t a[4], const uint32_t b[2]) {
    asm volatile(
        "mma.sync.aligned.m16n8k16.row.col.f32.bf16.bf16.f32 "
        "{%0,%1,%2,%3}, {%4,%5,%6,%7}, {%8,%9}, {%0,%1,%2,%3};"
        : "+f"(c[0]), "+f"(c[1]), "+f"(c[2]), "+f"(c[3])
        : "r"(a[0]), "r"(a[1]), "r"(a[2]), "r"(a[3]), "r"(b[0]), "r"(b[1]));
}
__device__ __forceinline__ void split2(float x0, float x1, uint32_t& hi, uint32_t& lo) {
    uint32_t h;
    asm("cvt.rn.bf16x2.f32 %0, %1, %2;" : "=r"(h) : "f"(x1), "f"(x0));
    float h0 = __uint_as_float(h << 16);
    float h1 = __uint_as_float(h & 0xffff0000u);
    float l0 = x0 - h0, l1 = x1 - h1;
    asm("cvt.rn.bf16x2.f32 %0, %1, %2;" : "=r"(lo) : "f"(l1), "f"(l0));
    hi = h;
}
__device__ __forceinline__ uint32_t ldm_addr(uint32_t base, int row0, int colbyte0, int lane) {
    int grp = lane >> 3, lr = lane & 7;
    uint32_t off = (uint32_t)((row0 + lr + (grp & 1) * 8) * 128 + colbyte0 + (grp >> 1) * 16);
    return base + sw128(off);
}
__device__ __forceinline__ void cpa16(uint32_t dst, const void* src) {
    asm volatile("cp.async.cg.shared.global [%0], [%1], 16;" :: "r"(dst), "l"(src));
}
#define CPA_COMMIT() asm volatile("cp.async.commit_group;" ::: "memory")
#define CPA_WAIT0()  asm volatile("cp.async.wait_group 0;" ::: "memory")

__device__ __forceinline__ unsigned f2ord(float f) {
    unsigned u = __float_as_uint(f);
    return (u & 0x80000000u) ? ~u : (u | 0x80000000u);
}
__device__ __forceinline__ float ord2f(unsigned u) {
    u = (u & 0x80000000u) ? (u ^ 0x80000000u) : ~u;
    return __uint_as_float(u);
}
__device__ __forceinline__ float sigmoidf_(float v) {
    return 1.0f / (1.0f + expf(-v));
}

// ---------------- threshold: parallel exact rank-select ----------------------
__global__ void kzero() {
    g_hist16[blockIdx.x * 1024 + threadIdx.x] = 0;
}
__global__ void khist16(const float* __restrict__ ap) {
    unsigned u = f2ord(ap[blockIdx.x * 1024 + threadIdx.x]);
    atomicAdd(&g_hist16[u >> 16], 1u);
}
__global__ void kselect(const float* __restrict__ ap) {
    __shared__ unsigned psum[1024];
    __shared__ unsigned s_bin, s_r, cnt;
    __shared__ unsigned cand[8192];
    int tid = threadIdx.x;
    unsigned s = 0;
#pragma unroll 8
    for (int i = 0; i < 64; i++) s += g_hist16[tid * 64 + i];
    psum[tid] = s;
    if (tid == 0) cnt = 0;
    __syncthreads();
    if (tid == 0) {
        unsigned cum = 0;
        int seg = 0;
        for (; seg < 1024; seg++) {
            if (cum + psum[seg] > (unsigned)RANK_K) break;
            cum += psum[seg];
        }
        unsigned r = RANK_K - cum;
        unsigned b = seg * 64;
        for (int i = 0; i < 64; i++) {
            unsigned h = g_hist16[seg * 64 + i];
            if (r < h) { b = seg * 64 + i; break; }
            r -= h;
        }
        s_bin = b;
        s_r = r;
    }
    __syncthreads();
    unsigned b = s_bin;
    for (int i = tid; i < 65536; i += 1024) {
        unsigned u = f2ord(ap[i]);
        if ((u >> 16) == b) {
            unsigned p = atomicAdd(&cnt, 1u);
            if (p < 8192) cand[p] = u;
        }
    }
    __syncthreads();
    unsigned c = min(cnt, 8192u);
    unsigned r = s_r;
    for (unsigned i = tid; i < c; i += 1024) {
        unsigned u = cand[i];
        unsigned less = 0, eq = 0;
        for (unsigned j = 0; j < c; j++) {
            less += (cand[j] < u) ? 1u : 0u;
            eq += (cand[j] == u) ? 1u : 0u;
        }
        if (less <= r && r < less + eq) g_thr = sigmoidf_(ord2f(u));
    }
}

// ---------------- kernel 2: adjacency build + output -------------------------
__global__ void kadj(const float* __restrict__ adj_param, float* __restrict__ out_adj) {
    int idx = blockIdx.x * blockDim.x + threadIdx.x;
    int i = idx >> 8, j = idx & 255;
    float s = sigmoidf_(adj_param[idx]);
    float a = (s > g_thr && i != j) ? s : 0.0f;
    g_adj[idx] = a;
    if (out_adj) out_adj[idx] = a;
}

// ---------------- kernel 3: effW1 = 0.5*(I + adj^T) @ G ----------------------
__global__ void keff(const float* __restrict__ gpW1) {
    __shared__ float adjs[32][36];
    __shared__ float Gs[32][132];
    int tx = threadIdx.x & 31;
    int ty = threadIdx.x >> 5;
    int de0 = blockIdx.x * 128;
    int j0 = blockIdx.y * 32;
    float acc[4][4] = {};
    for (int i0 = 0; i0 < NN; i0 += 32) {
        for (int l = threadIdx.x; l < 32 * 32; l += 256) {
            int ii = l >> 5, jj = l & 31;
            adjs[ii][jj] = g_adj[(i0 + ii) * NN + j0 + jj];
        }
        for (int l = threadIdx.x; l < 32 * 32; l += 256) {
            int ii = l >> 5, dq = (l & 31) * 4;
            float4 v = *reinterpret_cast<const float4*>(&gpW1[(size_t)(i0 + ii) * 4096 + de0 + dq]);
            *reinterpret_cast<float4*>(&Gs[ii][dq]) = v;
        }
        __syncthreads();
#pragma unroll
        for (int k = 0; k < 32; k++) {
            float4 a4 = *reinterpret_cast<const float4*>(&adjs[k][ty * 4]);
            float4 g4 = *reinterpret_cast<const float4*>(&Gs[k][tx * 4]);
            float av[4] = {a4.x, a4.y, a4.z, a4.w};
            float gv[4] = {g4.x, g4.y, g4.z, g4.w};
#pragma unroll
            for (int jj = 0; jj < 4; jj++)
#pragma unroll
                for (int dq = 0; dq < 4; dq++) acc[jj][dq] += av[jj] * gv[dq];
        }
        __syncthreads();
    }
#pragma unroll
    for (int jj = 0; jj < 4; jj++) {
        int j = j0 + ty * 4 + jj;
        int de = de0 + tx * 4;
        float4 gd = *reinterpret_cast<const float4*>(&gpW1[(size_t)j * 4096 + de]);
        float4 o;
        o.x = 0.5f * (gd.x + acc[jj][0]);
        o.y = 0.5f * (gd.y + acc[jj][1]);
        o.z = 0.5f * (gd.z + acc[jj][2]);
        o.w = 0.5f * (gd.w + acc[jj][3]);
        *reinterpret_cast<float4*>(&g_eff[(size_t)j * 4096 + de]) = o;
    }
}

// ---------------- kernel 3b: pre-split weights to swizzled bf16 --------------
// block (n, which): converts one 64x64 f32 tile to [hi 8KB | lo 8KB] swizzled.
__global__ void kprepW(const float* __restrict__ W1, const float* __restrict__ W2) {
    int n = blockIdx.x, which = blockIdx.y, tid = threadIdx.x;
    const float* src = (which == 0) ? W1 + (size_t)n * 4096
                     : (which == 1) ? W2 + (size_t)n * 4096
                                    : g_eff + (size_t)n * 4096;
    char* dst = g_wbf + ((size_t)which * NN + n) * 16384;
#pragma unroll
    for (int it = 0; it < 4; it++) {
        int l = tid + it * 128;          // group 0..511 (4 pairs each)
        int k = l >> 3, p4 = l & 7;
        const float4* s4 = reinterpret_cast<const float4*>(&src[k * 64 + p4 * 8]);
        float4 v0 = s4[0], v1 = s4[1];
        uint4 hi, lo;
        split2(v0.x, v0.y, hi.x, lo.x);
        split2(v0.z, v0.w, hi.y, lo.y);
        split2(v1.x, v1.y, hi.z, lo.z);
        split2(v1.z, v1.w, hi.w, lo.w);
        uint32_t off = sw128((uint32_t)(k * 128 + p4 * 16));
        *reinterpret_cast<uint4*>(dst + off) = hi;
        *reinterpret_cast<uint4*>(dst + 8192 + off) = lo;
    }
}

// ---------------- bf16x3 GEMM, hoisted fragments ------------------------------
// acc += Xhi@Whi + Xhi@Wlo + Xlo@Whi. W buffer at smem offset wb (hi @+0, lo @+8192).
__device__ __forceinline__ void wgemm(uint32_t sb, uint32_t wb, int w, int lane,
                                      float acc[2][8][4]) {
#pragma unroll
    for (int ks = 0; ks < 4; ks++) {
        uint32_t ahi[2][4], alo[2][4];
#pragma unroll
        for (int mt = 0; mt < 2; mt++) {
            ldm_x4(ahi[mt], ldm_addr(sb + SM_XHI, 32 * w + 16 * mt, 32 * ks, lane));
            ldm_x4(alo[mt], ldm_addr(sb + SM_XLO, 32 * w + 16 * mt, 32 * ks, lane));
        }
        uint32_t bhi[8][2], blo[8][2];
#pragma unroll
        for (int p = 0; p < 4; p++) {
            uint32_t r[4];
            ldm_x4_t(r, ldm_addr(sb + wb, 16 * ks, 32 * p, lane));
            bhi[2 * p][0] = r[0]; bhi[2 * p][1] = r[1];
            bhi[2 * p + 1][0] = r[2]; bhi[2 * p + 1][1] = r[3];
            ldm_x4_t(r, ldm_addr(sb + wb + 8192, 16 * ks, 32 * p, lane));
            blo[2 * p][0] = r[0]; blo[2 * p][1] = r[1];
            blo[2 * p + 1][0] = r[2]; blo[2 * p + 1][1] = r[3];
        }
#pragma unroll
        for (int mt = 0; mt < 2; mt++)
#pragma unroll
            for (int nt = 0; nt < 8; nt++) {
                mma16816(acc[mt][nt], ahi[mt], bhi[nt]);
                mma16816(acc[mt][nt], ahi[mt], blo[nt]);
                mma16816(acc[mt][nt], alo[mt], bhi[nt]);
            }
    }
}

// ---- async staging -----------------------------------------------------------
__device__ __forceinline__ void stageX(uint32_t sb, uint32_t stoff,
                                       const float* __restrict__ x,
                                       int b0, int n, int half, int tid) {
#pragma unroll
    for (int it = 0; it < 8; it++) {
        int ch = tid + it * 128;          // chunk 0..1023
        int r = ch >> 4, c16 = ch & 15;   // row-in-half, 16B chunk
        cpa16(sb + stoff + (uint32_t)(r * 256 + c16 * 16),
              &x[(size_t)(b0 + half * 64 + r) * (NN * DD) + n * DD + c16 * 4]);
    }
}
// copy a pre-split 16 KB W blob straight into a W ping-pong buffer
__device__ __forceinline__ void stageW16(uint32_t sb, uint32_t wb,
                                         const char* __restrict__ src, int tid) {
#pragma unroll
    for (int it = 0; it < 8; it++) {
        int off = (tid + it * 128) * 16;
        cpa16(sb + wb + off, src + off);
    }
}

// convert staged X -> XHI/XLO, 4 pairs (16B) per iteration, vectorized LDS/STS
__device__ __forceinline__ void convX_stage(char* smem, int tid) {
#pragma unroll
    for (int it = 0; it < 8; it++) {
        int l = tid + it * 128;          // group 0..1023 (4 pairs each)
        int r = l >> 3, p4 = l & 7;
        const float* st = reinterpret_cast<const float*>(smem + (r < 64 ? ST_X0 : ST_X1));
        const float4* src = reinterpret_cast<const float4*>(&st[(r & 63) * 64 + p4 * 8]);
        float4 v0 = src[0], v1 = src[1];
        uint4 hi, lo;
        split2(v0.x, v0.y, hi.x, lo.x);
        split2(v0.z, v0.w, hi.y, lo.y);
        split2(v1.x, v1.y, hi.z, lo.z);
        split2(v1.z, v1.w, hi.w, lo.w);
        uint32_t off = sw128((uint32_t)(r * 128 + p4 * 16));
        *reinterpret_cast<uint4*>(smem + SM_XHI + off) = hi;
        *reinterpret_cast<uint4*>(smem + SM_XLO + off) = lo;
    }
}

// epilogue: X <- (acc + bias) [relu], split into XHI/XLO (warp-private rows)
__device__ __forceinline__ void epilogue(char* smem, const float acc[2][8][4],
                                         const float* __restrict__ bias, bool relu,
                                         int w, int g, int tq) {
#pragma unroll
    for (int mt = 0; mt < 2; mt++) {
#pragma unroll
        for (int nt = 0; nt < 8; nt++) {
            int col = 8 * nt + 2 * tq;
            float2 bv = *reinterpret_cast<const float2*>(&bias[col]);
            float x0 = acc[mt][nt][0] + bv.x, x1 = acc[mt][nt][1] + bv.y;
            float x2 = acc[mt][nt][2] + bv.x, x3 = acc[mt][nt][3] + bv.y;
            if (relu) {
                x0 = fmaxf(x0, 0.0f); x1 = fmaxf(x1, 0.0f);
                x2 = fmaxf(x2, 0.0f); x3 = fmaxf(x3, 0.0f);
            }
            int row = 32 * w + 16 * mt + g;
            uint32_t hi, lo;
            split2(x0, x1, hi, lo);
            uint32_t off = sw128((uint32_t)(row * 128 + col * 2));
            *reinterpret_cast<uint32_t*>(smem + SM_XHI + off) = hi;
            *reinterpret_cast<uint32_t*>(smem + SM_XLO + off) = lo;
            split2(x2, x3, hi, lo);
            off = sw128((uint32_t)((row + 8) * 128 + col * 2));
            *reinterpret_cast<uint32_t*>(smem + SM_XHI + off) = hi;
            *reinterpret_cast<uint32_t*>(smem + SM_XLO + off) = lo;
        }
    }
}

// ---------------- fused tensor-core kernel (ping-pong W, 4 syncs/node) -------
// Block (bx, by): rows [bx*128,+128), nodes [by*8,+8). 128 threads, 4 warps.
__global__ void __launch_bounds__(128, 2) kfused_mma(
    const float* __restrict__ x,
    const float* __restrict__ b1, const float* __restrict__ b2) {
    extern __shared__ char smem[];
    uint32_t sb = smem_u32(smem);
    float* bias = reinterpret_cast<float*>(smem + SM_BIAS);   // [0:64)=b1, [64:128)=b2
    int tid = threadIdx.x, w = tid >> 5, lane = tid & 31;
    int g = lane >> 2, tq = lane & 3;
    int b0 = blockIdx.x * 128;
    int n0 = blockIdx.y * 8;

    const char* wb1 = g_wbf;                                   // W1 blobs
    const char* wb2 = g_wbf + (size_t)NN * 16384;               // W2 blobs
    const char* wbe = g_wbf + (size_t)2 * NN * 16384;           // eff blobs

    float acc_g[2][8][4] = {};
    uint32_t cur = SM_WB0, alt = SM_WB1;

    // prologue: stage X(n0) + W1(n0)
    stageX(sb, ST_X0, x, b0, n0, 0, tid);
    stageX(sb, ST_X1, x, b0, n0, 1, tid);
    stageW16(sb, cur, wb1 + (size_t)n0 * 16384, tid);
    CPA_COMMIT();
    CPA_WAIT0();
    __syncthreads();

    for (int nn = 0; nn < 8; nn++) {
        int n = n0 + nn;
        // ---- convert staged X(n); biases ----
        convX_stage(smem, tid);
        if (tid < 64) bias[tid] = b1[n * DD + tid];
        else bias[tid] = b2[n * DD + tid - 64];
        __syncthreads();                                       // sync1

        // G1: W2(n) -> alt, X(n+1) -> ST
        stageW16(sb, alt, wb2 + (size_t)n * 16384, tid);
        if (nn < 7) {
            stageX(sb, ST_X0, x, b0, n + 1, 0, tid);
            stageX(sb, ST_X1, x, b0, n + 1, 1, tid);
        }
        CPA_COMMIT();

        // ---- layer 1 (reads cur = W1) ----
        {
            float acc[2][8][4] = {};
            wgemm(sb, cur, w, lane, acc);
            CPA_WAIT0();
            __syncthreads();                                   // sync2
            epilogue(smem, acc, bias, true, w, g, tq);         // X <- relu(.+b1)
        }
        // G2: eff(n) -> cur (free after sync2)
        stageW16(sb, cur, wbe + (size_t)n * 16384, tid);
        CPA_COMMIT();

        // ---- layer 2 (reads alt = W2; X rows warp-private) ----
        {
            float acc[2][8][4] = {};
            wgemm(sb, alt, w, lane, acc);
            CPA_WAIT0();
            __syncthreads();                                   // sync3
            epilogue(smem, acc, bias + 64, false, w, g, tq);   // X <- node
        }
        // G3: W1(n+1) -> alt (free after sync3)
        if (nn < 7) {
            stageW16(sb, alt, wb1 + (size_t)(n + 1) * 16384, tid);
            CPA_COMMIT();
        }

        // ---- GEMM3: acc_g += node @ eff (reads cur) ----
        wgemm(sb, cur, w, lane, acc_g);
        CPA_WAIT0();
        __syncthreads();                                       // sync4

        uint32_t t = cur; cur = alt; alt = t;                  // next W1 is in alt
    }

    // ---- write partials ----
#pragma unroll
    for (int mt = 0; mt < 2; mt++) {
#pragma unroll
        for (int nt = 0; nt < 8; nt++) {
            int row = b0 + 32 * w + 16 * mt + g;
            int col = 8 * nt + 2 * tq;
            size_t base = ((size_t)blockIdx.y * BB + row) * 64 + col;
            float2 o0 = {acc_g[mt][nt][0], acc_g[mt][nt][1]};
            float2 o1 = {acc_g[mt][nt][2], acc_g[mt][nt][3]};
            *reinterpret_cast<float2*>(&g_parts[base]) = o0;
            *reinterpret_cast<float2*>(&g_parts[base + 8 * 64]) = o1;
        }
    }
}

// ---------------- kernel: reduce partials + relu + gpW2 epilogue -------------
__global__ void kfinal(const float* __restrict__ gpb1, const float* __restrict__ gpW2,
                       const float* __restrict__ gpb2, float* __restrict__ out) {
    __shared__ float gs[FB][65];
    __shared__ float w2s[64][33];
    __shared__ float b2s[32];
    int b0 = blockIdx.x * FB;
    for (int l = threadIdx.x; l < FB * 64; l += 256) {
        int r = l >> 6, d = l & 63;
        float s = gpb1[d];
#pragma unroll
        for (int ks = 0; ks < NCHUNK; ks++) s += g_parts[((size_t)ks * BB + b0 + r) * 64 + d];
        gs[r][d] = fmaxf(s, 0.0f);
    }
    for (int l = threadIdx.x; l < 2048; l += 256) {
        int d = l >> 5, h = l & 31;
        w2s[d][h] = gpW2[l];
    }
    if (threadIdx.x < 32) b2s[threadIdx.x] = gpb2[threadIdx.x];
    __syncthreads();
    int h = threadIdx.x & 31, rg = threadIdx.x >> 5;
#pragma unroll
    for (int i = 0; i < FB / 8; i++) {
        int r = rg * (FB / 8) + i;
        float s = b2s[h];
#pragma unroll 16
        for (int d = 0; d < 64; d++) s += gs[r][d] * w2s[d][h];
        out[(size_t)(b0 + r) * 32 + h] = s;
    }
}

// ---------------- launch ------------------------------------------------------
extern "C" void kernel_launch(void* const* d_in, const int* in_sizes, int n_in,
                              void* d_out, int out_size) {
    const float* x         = (const float*)d_in[0];
    const float* adj_param = (const float*)d_in[1];
    const float* W1        = (const float*)d_in[2];
    const float* b1        = (const float*)d_in[3];
    const float* W2        = (const float*)d_in[4];
    const float* b2        = (const float*)d_in[5];
    const float* gpW1      = (const float*)d_in[6];
    const float* gpb1      = (const float*)d_in[7];
    const float* gpW2      = (const float*)d_in[8];
    const float* gpb2      = (const float*)d_in[9];
    float* out = (float*)d_out;
    float* adj_out = (out_size >= 131072) ? (out + BB * 32) : nullptr;

    cudaFuncSetAttribute(kfused_mma, cudaFuncAttributeMaxDynamicSharedMemorySize, SM_TOT);

    kzero<<<64, 1024>>>();
    khist16<<<64, 1024>>>(adj_param);
    kselect<<<1, 1024>>>(adj_param);
    kadj<<<64, 1024>>>(adj_param, adj_out);
    keff<<<dim3(32, 8), 256>>>(gpW1);
    kprepW<<<dim3(NN, 3), 128>>>(W1, W2);
    kfused_mma<<<dim3(BB / 128, NCHUNK), 128, SM_TOT>>>(x, b1, b2);
    kfinal<<<BB / FB, 256>>>(gpb1, gpW2, gpb2, out);
}